// round 1
// baseline (speedup 1.0000x reference)
#include <cuda_runtime.h>
#include <math.h>

#define Bb 2
#define Cc 64
#define Hh 384
#define Ww 384
#define HW (Hh*Ww)            // 147456
#define NTOT (Bb*Cc*HW)       // 18874368
#define HH 48
#define WW 48
#define LLEN HW               // 147456 (= 48*48*64)
#define NPATCH (Bb*Cc*HH*WW)  // 294912

// ------------------- scratch (device globals: allowed) -------------------
__device__ float g_bA[NTOT];      // hidden -> out(proj_mid)
__device__ float g_bB[2*NTOT];    // nir_hidden
__device__ float g_bC[NTOT];      // q -> u1
__device__ float g_bD[2*NTOT];    // kv -> pool accumulator
__device__ float g_bE[NTOT];      // qfft -> o_freq -> t2
__device__ float g_bF[NTOT];      // kfft -> o_spatial -> u2
__device__ float g_bG[NTOT];      // out1 -> t1

__device__ float g_DCTM[64];      // [a*8+m]
__device__ float g_IDCTM[64];     // [m*8+a]
__device__ float g_sqq[128];
__device__ float g_sqk[128];
__device__ float g_S[8*256];
__device__ float g_attn[8*256];
__device__ float g_lam;

// ------------------- init: DCT matrices, lambda, zero accumulators -------
__global__ void k_init(const float* __restrict__ lq1, const float* __restrict__ lk1,
                       const float* __restrict__ lq2, const float* __restrict__ lk2)
{
    int t = threadIdx.x;  // 64 threads
    if (t < 64) {
        int a = t >> 3, m = t & 7;
        double cv = 2.0 * cos(3.14159265358979323846 * (double)((2*m+1)*a) / 16.0);
        g_DCTM[a*8+m] = (float)cv;
        // C*C^T = diag(32,16,...,16)  =>  inv(C) = C^T * D^-1
        g_IDCTM[m*8+a] = (float)(cv / (a == 0 ? 32.0 : 16.0));
    }
    if (t < 32) {
        float s1 = lq1[t]*lk1[t] + lq1[t+32]*lk1[t+32];
        float s2 = lq2[t]*lk2[t] + lq2[t+32]*lk2[t+32];
        #pragma unroll
        for (int off = 16; off; off >>= 1) {
            s1 += __shfl_xor_sync(0xffffffffu, s1, off);
            s2 += __shfl_xor_sync(0xffffffffu, s2, off);
        }
        if (t == 0) {
            float lam_init = 0.8f - 0.6f * (float)exp(-1.8);  // DEPTH=6
            g_lam = expf(s1) - expf(s2) + lam_init;
        }
    }
    for (int i = t; i < 2048; i += 64) g_S[i] = 0.f;
    for (int i = t; i < 128;  i += 64) { g_sqq[i] = 0.f; g_sqk[i] = 0.f; }
}

// ------------------- conv1x1: out[b,oc,p] = sum_i w[oc,i] * in[b,i,p] ----
// IC fixed at 64. grid = (HW/512, B, OCtot/64), 256 thr, 2 pixels/thread.
__global__ void __launch_bounds__(256) k_conv1x1(
    const float* __restrict__ in, const float* __restrict__ w,
    float* __restrict__ out, int OCtot)
{
    __shared__ float ws[64*64];
    int ocBase = blockIdx.z * 64;
    int b = blockIdx.y;
    int tid = threadIdx.x;
    for (int t = tid; t < 64*64; t += 256) {
        int j = t >> 6, i = t & 63;
        ws[t] = w[(ocBase + j)*64 + i];
    }
    __syncthreads();
    const float* inb = in + b*64*HW;
    float* outb = out + b*OCtot*HW + ocBase*HW;
    int p0 = blockIdx.x*512 + tid;
    int p1 = p0 + 256;
    float acc0[64], acc1[64];
    #pragma unroll
    for (int j = 0; j < 64; j++) { acc0[j] = 0.f; acc1[j] = 0.f; }
    #pragma unroll 4
    for (int i = 0; i < 64; i++) {
        float x0 = inb[i*HW + p0];
        float x1 = inb[i*HW + p1];
        #pragma unroll
        for (int j = 0; j < 64; j++) {
            float wv = ws[j*64 + i];
            acc0[j] += wv * x0;
            acc1[j] += wv * x1;
        }
    }
    #pragma unroll
    for (int j = 0; j < 64; j++) {
        outb[j*HW + p0] = acc0[j];
        outb[j*HW + p1] = acc1[j];
    }
}

// ------------------- depthwise 3x3, SAME pad, optional prelu/accumulate --
__global__ void k_dw3(const float* __restrict__ in, const float* __restrict__ w9,
                      float* __restrict__ out, int CHtot,
                      const float* __restrict__ prelu_a, int accum)
{
    int idx = blockIdx.x*256 + threadIdx.x;
    int x = idx % Ww;
    int y = (idx / Ww) % Hh;
    int bc = idx / HW;
    int ch = bc & (CHtot - 1);   // CHtot is 64 or 128
    const float* ip = in + bc*HW;
    const float* wp = w9 + ch*9;
    float s = 0.f;
    #pragma unroll
    for (int dy = -1; dy <= 1; dy++) {
        int yy = y + dy;
        if ((unsigned)yy < (unsigned)Hh) {
            const float* row = ip + yy*Ww;
            #pragma unroll
            for (int dx = -1; dx <= 1; dx++) {
                int xx = x + dx;
                if ((unsigned)xx < (unsigned)Ww)
                    s += wp[(dy+1)*3 + (dx+1)] * row[xx];
            }
        }
    }
    if (prelu_a) { float a = *prelu_a; s = (s >= 0.f) ? s : a*s; }
    if (accum) out[idx] += s; else out[idx] = s;
}

// ------------------- DCT per 8x8 patch: Y = C X C^T ----------------------
// freq layout: [(bc*48+ph)*48+pw]*64 + a*8 + bb  (== patch index p * 64)
__global__ void k_dct(const float* __restrict__ in, float* __restrict__ outf, int inChTot)
{
    __shared__ float M[64];
    if (threadIdx.x < 64) M[threadIdx.x] = g_DCTM[threadIdx.x];
    __syncthreads();
    int p = blockIdx.x*128 + threadIdx.x;
    int pw = p % WW;
    int t2 = p / WW;
    int ph = t2 % HH;
    int bc = t2 / HH;
    int b = bc >> 6, ch = bc & 63;
    const float* ip = in + (b*inChTot + ch)*HW + ph*8*Ww + pw*8;
    float tmp[8][8];
    #pragma unroll
    for (int m = 0; m < 8; m++) {
        float4 v0 = *(const float4*)(ip + m*Ww);
        float4 v1 = *(const float4*)(ip + m*Ww + 4);
        float r[8] = {v0.x, v0.y, v0.z, v0.w, v1.x, v1.y, v1.z, v1.w};
        #pragma unroll
        for (int bb = 0; bb < 8; bb++) {
            float s = 0.f;
            #pragma unroll
            for (int n = 0; n < 8; n++) s += r[n] * M[bb*8+n];
            tmp[m][bb] = s;
        }
    }
    float* op = outf + p*64;
    #pragma unroll
    for (int a = 0; a < 8; a++) {
        float y[8];
        #pragma unroll
        for (int bb = 0; bb < 8; bb++) {
            float s = 0.f;
            #pragma unroll
            for (int m = 0; m < 8; m++) s += M[a*8+m] * tmp[m][bb];
            y[bb] = s;
        }
        *(float4*)(op + a*8)     = make_float4(y[0], y[1], y[2], y[3]);
        *(float4*)(op + a*8 + 4) = make_float4(y[4], y[5], y[6], y[7]);
    }
}

// ------------------- IDCT per patch: Y = Ci X Ci^T, write spatial --------
__global__ void k_idct(const float* __restrict__ inf, float* __restrict__ out)
{
    __shared__ float M[64];   // IDCTM[m*8+a]
    if (threadIdx.x < 64) M[threadIdx.x] = g_IDCTM[threadIdx.x];
    __syncthreads();
    int p = blockIdx.x*128 + threadIdx.x;
    int pw = p % WW;
    int t2 = p / WW;
    int ph = t2 % HH;
    int bc = t2 / HH;
    const float* ip = inf + p*64;
    float X[8][8];
    #pragma unroll
    for (int a = 0; a < 8; a++) {
        float4 v0 = *(const float4*)(ip + a*8);
        float4 v1 = *(const float4*)(ip + a*8 + 4);
        X[a][0]=v0.x; X[a][1]=v0.y; X[a][2]=v0.z; X[a][3]=v0.w;
        X[a][4]=v1.x; X[a][5]=v1.y; X[a][6]=v1.z; X[a][7]=v1.w;
    }
    float tmp[8][8];  // tmp[a][n] = sum_b X[a][b]*Ci[n][b]
    #pragma unroll
    for (int a = 0; a < 8; a++) {
        #pragma unroll
        for (int n = 0; n < 8; n++) {
            float s = 0.f;
            #pragma unroll
            for (int bq = 0; bq < 8; bq++) s += X[a][bq] * M[n*8+bq];
            tmp[a][n] = s;
        }
    }
    float* op = out + bc*HW + ph*8*Ww + pw*8;
    #pragma unroll
    for (int m = 0; m < 8; m++) {
        float y[8];
        #pragma unroll
        for (int n = 0; n < 8; n++) {
            float s = 0.f;
            #pragma unroll
            for (int a = 0; a < 8; a++) s += M[m*8+a] * tmp[a][n];
            y[n] = s;
        }
        *(float4*)(op + m*Ww)     = make_float4(y[0], y[1], y[2], y[3]);
        *(float4*)(op + m*Ww + 4) = make_float4(y[4], y[5], y[6], y[7]);
    }
}

// ------------------- out1 = qf*kf; accumulate per-channel sumsq ----------
__global__ void k_mulsq(const float* __restrict__ qf, const float* __restrict__ kf,
                        float* __restrict__ out1)
{
    int idx = blockIdx.x*256 + threadIdx.x;
    float qv = qf[idx], kv = kf[idx];
    out1[idx] = qv * kv;
    float sq = qv*qv, sk = kv*kv;
    #pragma unroll
    for (int off = 16; off; off >>= 1) {
        sq += __shfl_xor_sync(0xffffffffu, sq, off);
        sk += __shfl_xor_sync(0xffffffffu, sk, off);
    }
    __shared__ float aq[8], ak[8];
    int lane = threadIdx.x & 31, wd = threadIdx.x >> 5;
    if (lane == 0) { aq[wd] = sq; ak[wd] = sk; }
    __syncthreads();
    if (threadIdx.x == 0) {
        float tq = 0.f, tk = 0.f;
        #pragma unroll
        for (int i = 0; i < 8; i++) { tq += aq[i]; tk += ak[i]; }
        int row = (blockIdx.x*256) / LLEN;   // block never crosses a row (L%256==0)
        atomicAdd(&g_sqq[row], tq);
        atomicAdd(&g_sqk[row], tk);
    }
}

// ------------------- raw Gram matrices S[bh][c][d] = <qf_c, kf_d> --------
__global__ void k_dot(const float* __restrict__ qf, const float* __restrict__ kf)
{
    int bh = blockIdx.y; int b = bh >> 2, h = bh & 3;
    const float* qb = qf + (b*64 + h*16)*LLEN;
    const float* kb = kf + (b*64 + h*16)*LLEN;
    int tid = threadIdx.x;
    int c = tid >> 4, d = tid & 15;
    __shared__ float qs[16][65], ks[16][65];
    float acc = 0.f;
    int l0 = blockIdx.x * 4096;   // 36 blocks cover L=147456
    for (int lt = 0; lt < 4096; lt += 64) {
        int base = l0 + lt;
        for (int t = tid; t < 1024; t += 256) {
            int r = t >> 6, i = t & 63;
            qs[r][i] = qb[r*LLEN + base + i];
            ks[r][i] = kb[r*LLEN + base + i];
        }
        __syncthreads();
        #pragma unroll
        for (int i = 0; i < 64; i++) acc += qs[c][i] * ks[d][i];
        __syncthreads();
    }
    atomicAdd(&g_S[bh*256 + tid], acc);
}

// ------------------- finalize logits + softmax over d --------------------
__global__ void k_softmax(const float* __restrict__ temp)
{
    int bh = blockIdx.x; int b = bh >> 2, h = bh & 3;
    int tid = threadIdx.x; int c = tid >> 4, d = tid & 15;
    float nq = fmaxf(sqrtf(g_sqq[b*64 + h*16 + c]), 1e-12f);
    float nk = fmaxf(sqrtf(g_sqk[b*64 + h*16 + d]), 1e-12f);
    float logit = g_S[bh*256 + tid] / (nq*nk) * temp[h];
    float mx = logit;
    #pragma unroll
    for (int off = 8; off; off >>= 1)
        mx = fmaxf(mx, __shfl_xor_sync(0xffffffffu, mx, off, 16));
    float e = expf(logit - mx);
    float s = e;
    #pragma unroll
    for (int off = 8; off; off >>= 1)
        s += __shfl_xor_sync(0xffffffffu, s, off, 16);
    g_attn[bh*256 + tid] = e / s;
}

// ------------------- o[c][l] = sum_d attn[c][d]*out1[d][l] ---------------
__global__ void k_apply(const float* __restrict__ out1, float* __restrict__ o)
{
    int bh = blockIdx.y; int b = bh >> 2, h = bh & 3;
    __shared__ float as_[256];
    as_[threadIdx.x] = g_attn[bh*256 + threadIdx.x];
    __syncthreads();
    int l = blockIdx.x*256 + threadIdx.x;
    int base = (b*64 + h*16)*LLEN + l;
    float xv[16];
    #pragma unroll
    for (int dd = 0; dd < 16; dd++) xv[dd] = out1[base + dd*LLEN];
    #pragma unroll
    for (int cc = 0; cc < 16; cc++) {
        float acc = 0.f;
        #pragma unroll
        for (int dd = 0; dd < 16; dd++) acc += as_[cc*16 + dd] * xv[dd];
        o[base + cc*LLEN] = acc;
    }
}

// ------------------- t1 = q*out ; t2 = v - lam*(v*out) -------------------
__global__ void k_elem(const float* __restrict__ q, const float* __restrict__ om,
                       const float* __restrict__ kv,
                       float* __restrict__ t1, float* __restrict__ t2)
{
    int idx = blockIdx.x*256 + threadIdx.x;
    int b = idx / (64*HW);
    int rem = idx - b*64*HW;
    float ov = om[idx], qv = q[idx];
    t1[idx] = qv * ov;
    float vv = kv[b*128*HW + 64*HW + rem];
    t2[idx] = vv - g_lam * (vv * ov);
}

// ------------------- host launcher --------------------------------------
extern "C" void kernel_launch(void* const* d_in, const int* in_sizes, int n_in,
                              void* d_out, int out_size)
{
    const float* x            = (const float*)d_in[0];
    const float* nir          = (const float*)d_in[1];
    const float* w_hidden     = (const float*)d_in[2];
    const float* w_hidden_nir = (const float*)d_in[3];
    const float* w_dw         = (const float*)d_in[4];
    const float* w_dw_nir     = (const float*)d_in[5];
    const float* temperature  = (const float*)d_in[6];
    const float* w_proj_mid   = (const float*)d_in[7];
    const float* w_proj_out   = (const float*)d_in[8];
    const float* w_p1a        = (const float*)d_in[9];
    const float* a_p1         = (const float*)d_in[10];
    const float* w_p1b        = (const float*)d_in[11];
    const float* w_p2a        = (const float*)d_in[12];
    const float* a_p2         = (const float*)d_in[13];
    const float* w_p2b        = (const float*)d_in[14];
    const float* lq1          = (const float*)d_in[15];
    const float* lk1          = (const float*)d_in[16];
    const float* lq2          = (const float*)d_in[17];
    const float* lk2          = (const float*)d_in[18];

    float *A, *Bf, *Cf, *D, *E, *F, *G;
    cudaGetSymbolAddress((void**)&A,  g_bA);
    cudaGetSymbolAddress((void**)&Bf, g_bB);
    cudaGetSymbolAddress((void**)&Cf, g_bC);
    cudaGetSymbolAddress((void**)&D,  g_bD);
    cudaGetSymbolAddress((void**)&E,  g_bE);
    cudaGetSymbolAddress((void**)&F,  g_bF);
    cudaGetSymbolAddress((void**)&G,  g_bG);

    // constants + lambda + zero accumulators (every call: deterministic)
    k_init<<<1, 64>>>(lq1, lk1, lq2, lk2);

    // hidden = W_h @ x ; nir_hidden = W_hn @ nir
    k_conv1x1<<<dim3(HW/512, Bb, 1), 256>>>(x,   w_hidden,     A,  64);
    k_conv1x1<<<dim3(HW/512, Bb, 2), 256>>>(nir, w_hidden_nir, Bf, 128);

    // q = dw3(hidden) ; kv = dw3(nir_hidden)
    k_dw3<<<NTOT/256,   256>>>(A,  w_dw,     Cf, 64,  nullptr, 0);
    k_dw3<<<2*NTOT/256, 256>>>(Bf, w_dw_nir, D,  128, nullptr, 0);

    // q_fft, k_fft (k = kv channels [0,64) per batch)
    k_dct<<<NPATCH/128, 128>>>(Cf, E, 64);
    k_dct<<<NPATCH/128, 128>>>(D,  F, 128);

    // out1 = q_fft*k_fft ; per-channel sumsq for norms
    k_mulsq<<<NTOT/256, 256>>>(E, F, G);

    // attention: Gram -> normalize/temp/softmax -> apply to out1
    k_dot<<<dim3(36, 8), 256>>>(E, F);
    k_softmax<<<8, 256>>>(temperature);
    k_apply<<<dim3(LLEN/256, 8), 256>>>(G, E);   // o_freq into E

    // idct + un-patch -> spatial o (F); out = W_pm @ o (A)
    k_idct<<<NPATCH/128, 128>>>(E, F);
    k_conv1x1<<<dim3(HW/512, Bb, 1), 256>>>(F, w_proj_mid, A, 64);

    // t1 = q*out (G) ; t2 = v - lam*(v*out) (E)
    k_elem<<<NTOT/256, 256>>>(Cf, A, D, G, E);

    // pools: u = prelu(dw3(t, wa), a) ; acc = dw3(u1,w1b) + dw3(u2,w2b)
    k_dw3<<<NTOT/256, 256>>>(G, w_p1a, Cf, 64, a_p1, 0);
    k_dw3<<<NTOT/256, 256>>>(E, w_p2a, F,  64, a_p2, 0);
    k_dw3<<<NTOT/256, 256>>>(Cf, w_p1b, D, 64, nullptr, 0);
    k_dw3<<<NTOT/256, 256>>>(F,  w_p2b, D, 64, nullptr, 1);

    // final projection into d_out
    k_conv1x1<<<dim3(HW/512, Bb, 1), 256>>>(D, w_proj_out, (float*)d_out, 64);
}

// round 2
// speedup vs baseline: 1.3376x; 1.3376x over previous
#include <cuda_runtime.h>
#include <math.h>

#define Bb 2
#define Cc 64
#define Hh 384
#define Ww 384
#define HW (Hh*Ww)            // 147456
#define NTOT (Bb*Cc*HW)       // 18874368
#define HH 48
#define WW 48
#define LLEN HW               // 147456
#define NPATCH (Bb*Cc*HH*WW)  // 294912

typedef unsigned long long ull;

// ------------------- scratch (device globals) -----------------------------
__device__ float g_bA[NTOT];      // hidden -> out(proj_mid)
__device__ float g_bB[2*NTOT];    // nir_hidden
__device__ float g_bC[NTOT];      // q
__device__ float g_bD[2*NTOT];    // kv
__device__ float g_bE[NTOT];      // qf -> o_freq -> u1
__device__ float g_bF[NTOT];      // kf -> o_spatial -> u2
__device__ float g_bG[NTOT];      // out1 -> pooled output

__device__ float g_DCTM[64];      // [a*8+m]
__device__ float g_IDCTM[64];     // [m*8+a]
__device__ float g_sqq[128];
__device__ float g_sqk[128];
__device__ float g_S[8*256];
__device__ float g_attn[8*256];
__device__ float g_lam;

// ------------------- packed f32x2 helpers (sm_100+) -----------------------
__device__ __forceinline__ ull pk2(float lo, float hi) {
    ull r; asm("mov.b64 %0, {%1,%2};" : "=l"(r) : "f"(lo), "f"(hi)); return r;
}
__device__ __forceinline__ void upk2(float& lo, float& hi, ull v) {
    asm("mov.b64 {%0,%1}, %2;" : "=f"(lo), "=f"(hi) : "l"(v));
}
#define FMA2(d, a, b, c) asm("fma.rn.f32x2 %0, %1, %2, %3;" : "=l"(d) : "l"(a), "l"(b), "l"(c))

// ------------------- init: DCT matrices, lambda, zero accumulators --------
__global__ void k_init(const float* __restrict__ lq1, const float* __restrict__ lk1,
                       const float* __restrict__ lq2, const float* __restrict__ lk2)
{
    int t = threadIdx.x;  // 64 threads
    if (t < 64) {
        int a = t >> 3, m = t & 7;
        double cv = 2.0 * cos(3.14159265358979323846 * (double)((2*m+1)*a) / 16.0);
        g_DCTM[a*8+m] = (float)cv;
        g_IDCTM[m*8+a] = (float)(cv / (a == 0 ? 32.0 : 16.0));
    }
    if (t < 32) {
        float s1 = lq1[t]*lk1[t] + lq1[t+32]*lk1[t+32];
        float s2 = lq2[t]*lk2[t] + lq2[t+32]*lk2[t+32];
        #pragma unroll
        for (int off = 16; off; off >>= 1) {
            s1 += __shfl_xor_sync(0xffffffffu, s1, off);
            s2 += __shfl_xor_sync(0xffffffffu, s2, off);
        }
        if (t == 0) {
            float lam_init = 0.8f - 0.6f * (float)exp(-1.8);
            g_lam = expf(s1) - expf(s2) + lam_init;
        }
    }
    for (int i = t; i < 2048; i += 64) g_S[i] = 0.f;
    for (int i = t; i < 128;  i += 64) { g_sqq[i] = 0.f; g_sqk[i] = 0.f; }
}

// ------------------- conv1x1 with packed FFMA2 ----------------------------
// out[b,oc,p] = sum_i w[oc,i]*in[b,i,p], IC=64.
// block 256 thr: oh = tid>>7 selects 32-oc half, (tid&127) -> 4 pixels.
// grid = (HW/512, B, OCtot/64)
__global__ void __launch_bounds__(256) k_conv1x1(
    const float* __restrict__ in, const float* __restrict__ w,
    float* __restrict__ out, int OCtot)
{
    __shared__ ull ws[64*64];     // (w,w) packed, [oc][k], 32KB
    int ocBase = blockIdx.z * 64;
    int b = blockIdx.y;
    int tid = threadIdx.x;
    for (int t = tid; t < 4096; t += 256) {
        int j = t >> 6, i = t & 63;
        float wv = w[(ocBase + j)*64 + i];
        ws[t] = pk2(wv, wv);
    }
    __syncthreads();
    const float* inb = in + (size_t)b*64*HW;
    int oh = tid >> 7;
    int p0 = blockIdx.x*512 + (tid & 127)*4;
    ull accA[32], accB[32];
    #pragma unroll
    for (int j = 0; j < 32; j++) { accA[j] = 0ULL; accB[j] = 0ULL; }
    const ull* wrow = ws + oh*32*64;
    #pragma unroll 2
    for (int i = 0; i < 64; i++) {
        float4 xv = *(const float4*)(inb + (size_t)i*HW + p0);
        ull xA = pk2(xv.x, xv.y);
        ull xB = pk2(xv.z, xv.w);
        #pragma unroll
        for (int j = 0; j < 32; j++) {
            ull wv = wrow[j*64 + i];
            FMA2(accA[j], wv, xA, accA[j]);
            FMA2(accB[j], wv, xB, accB[j]);
        }
    }
    float* outb = out + ((size_t)b*OCtot + ocBase + oh*32)*HW;
    #pragma unroll
    for (int j = 0; j < 32; j++) {
        float o0, o1, o2, o3;
        upk2(o0, o1, accA[j]);
        upk2(o2, o3, accB[j]);
        *(float4*)(outb + (size_t)j*HW + p0) = make_float4(o0, o1, o2, o3);
    }
}

// ------------------- row loader: 6 values around aligned 4-px group -------
__device__ __forceinline__ void load6(const float* __restrict__ row, int x, float v[6])
{
    float4 c = *(const float4*)(row + x);
    v[1] = c.x; v[2] = c.y; v[3] = c.z; v[4] = c.w;
    v[0] = (x > 0)      ? row[x-1] : 0.f;
    v[5] = (x+4 < Ww)   ? row[x+4] : 0.f;
}

// ------------------- depthwise 3x3, 4 px/thread ---------------------------
__global__ void __launch_bounds__(256) k_dw3v(
    const float* __restrict__ in, const float* __restrict__ w9,
    float* __restrict__ out, int chMask)
{
    int g = blockIdx.x*256 + threadIdx.x;
    int px = g*4;
    int x = px % Ww;
    int y = (px / Ww) % Hh;
    int bc = px / HW;
    int ch = bc & chMask;
    const float* ip = in + (size_t)bc*HW;
    float w[9];
    #pragma unroll
    for (int i = 0; i < 9; i++) w[i] = __ldg(w9 + ch*9 + i);
    float acc[4] = {0.f, 0.f, 0.f, 0.f};
    #pragma unroll
    for (int dy = -1; dy <= 1; dy++) {
        int yy = y + dy;
        if ((unsigned)yy < (unsigned)Hh) {
            float v[6];
            load6(ip + yy*Ww, x, v);
            const float* wr = w + (dy+1)*3;
            #pragma unroll
            for (int j = 0; j < 4; j++)
                acc[j] += wr[0]*v[j] + wr[1]*v[j+1] + wr[2]*v[j+2];
        }
    }
    *(float4*)(out + px) = make_float4(acc[0], acc[1], acc[2], acc[3]);
}

// ------------------- DCT(q): Y = C X C^T, write qf, accumulate sumsq ------
// one thread per 8x8 patch; blocks of 128 never cross channels (2304%128==0)
__global__ void k_dctq(const float* __restrict__ in, float* __restrict__ qf)
{
    __shared__ float M[64];
    __shared__ float red[4];
    if (threadIdx.x < 64) M[threadIdx.x] = g_DCTM[threadIdx.x];
    __syncthreads();
    int p = blockIdx.x*128 + threadIdx.x;
    int pw = p % WW;
    int t2 = p / WW;
    int ph = t2 % HH;
    int bc = t2 / HH;
    const float* ip = in + (size_t)bc*HW + ph*8*Ww + pw*8;
    float tmp[8][8];
    #pragma unroll
    for (int m = 0; m < 8; m++) {
        float4 v0 = *(const float4*)(ip + m*Ww);
        float4 v1 = *(const float4*)(ip + m*Ww + 4);
        float r[8] = {v0.x, v0.y, v0.z, v0.w, v1.x, v1.y, v1.z, v1.w};
        #pragma unroll
        for (int bb = 0; bb < 8; bb++) {
            float s = 0.f;
            #pragma unroll
            for (int n = 0; n < 8; n++) s += r[n] * M[bb*8+n];
            tmp[m][bb] = s;
        }
    }
    float* op = qf + (size_t)p*64;
    float ss = 0.f;
    #pragma unroll
    for (int a = 0; a < 8; a++) {
        float y[8];
        #pragma unroll
        for (int bb = 0; bb < 8; bb++) {
            float s = 0.f;
            #pragma unroll
            for (int m = 0; m < 8; m++) s += M[a*8+m] * tmp[m][bb];
            y[bb] = s;
            ss += s*s;
        }
        *(float4*)(op + a*8)     = make_float4(y[0], y[1], y[2], y[3]);
        *(float4*)(op + a*8 + 4) = make_float4(y[4], y[5], y[6], y[7]);
    }
    #pragma unroll
    for (int off = 16; off; off >>= 1) ss += __shfl_xor_sync(0xffffffffu, ss, off);
    if ((threadIdx.x & 31) == 0) red[threadIdx.x >> 5] = ss;
    __syncthreads();
    if (threadIdx.x == 0)
        atomicAdd(&g_sqq[bc], red[0]+red[1]+red[2]+red[3]);
}

// ------------------- DCT(k): write kf, out1 = qf*kf, accumulate sumsq -----
__global__ void k_dctk(const float* __restrict__ kv, const float* __restrict__ qf,
                       float* __restrict__ kf, float* __restrict__ out1)
{
    __shared__ float M[64];
    __shared__ float red[4];
    if (threadIdx.x < 64) M[threadIdx.x] = g_DCTM[threadIdx.x];
    __syncthreads();
    int p = blockIdx.x*128 + threadIdx.x;
    int pw = p % WW;
    int t2 = p / WW;
    int ph = t2 % HH;
    int bc = t2 / HH;
    int b = bc >> 6, ch = bc & 63;
    const float* ip = kv + ((size_t)b*128 + ch)*HW + ph*8*Ww + pw*8;
    float tmp[8][8];
    #pragma unroll
    for (int m = 0; m < 8; m++) {
        float4 v0 = *(const float4*)(ip + m*Ww);
        float4 v1 = *(const float4*)(ip + m*Ww + 4);
        float r[8] = {v0.x, v0.y, v0.z, v0.w, v1.x, v1.y, v1.z, v1.w};
        #pragma unroll
        for (int bb = 0; bb < 8; bb++) {
            float s = 0.f;
            #pragma unroll
            for (int n = 0; n < 8; n++) s += r[n] * M[bb*8+n];
            tmp[m][bb] = s;
        }
    }
    float* kp = kf + (size_t)p*64;
    float* o1 = out1 + (size_t)p*64;
    const float* qp = qf + (size_t)p*64;
    float ss = 0.f;
    #pragma unroll
    for (int a = 0; a < 8; a++) {
        float y[8];
        #pragma unroll
        for (int bb = 0; bb < 8; bb++) {
            float s = 0.f;
            #pragma unroll
            for (int m = 0; m < 8; m++) s += M[a*8+m] * tmp[m][bb];
            y[bb] = s;
            ss += s*s;
        }
        float4 q0 = *(const float4*)(qp + a*8);
        float4 q1 = *(const float4*)(qp + a*8 + 4);
        *(float4*)(kp + a*8)     = make_float4(y[0], y[1], y[2], y[3]);
        *(float4*)(kp + a*8 + 4) = make_float4(y[4], y[5], y[6], y[7]);
        *(float4*)(o1 + a*8)     = make_float4(q0.x*y[0], q0.y*y[1], q0.z*y[2], q0.w*y[3]);
        *(float4*)(o1 + a*8 + 4) = make_float4(q1.x*y[4], q1.y*y[5], q1.z*y[6], q1.w*y[7]);
    }
    #pragma unroll
    for (int off = 16; off; off >>= 1) ss += __shfl_xor_sync(0xffffffffu, ss, off);
    if ((threadIdx.x & 31) == 0) red[threadIdx.x >> 5] = ss;
    __syncthreads();
    if (threadIdx.x == 0)
        atomicAdd(&g_sqk[bc], red[0]+red[1]+red[2]+red[3]);
}

// ------------------- IDCT per patch: Y = Ci X Ci^T, write spatial ---------
__global__ void k_idct(const float* __restrict__ inf, float* __restrict__ out)
{
    __shared__ float M[64];   // IDCTM[m*8+a]
    if (threadIdx.x < 64) M[threadIdx.x] = g_IDCTM[threadIdx.x];
    __syncthreads();
    int p = blockIdx.x*128 + threadIdx.x;
    int pw = p % WW;
    int t2 = p / WW;
    int ph = t2 % HH;
    int bc = t2 / HH;
    const float* ip = inf + (size_t)p*64;
    float X[8][8];
    #pragma unroll
    for (int a = 0; a < 8; a++) {
        float4 v0 = *(const float4*)(ip + a*8);
        float4 v1 = *(const float4*)(ip + a*8 + 4);
        X[a][0]=v0.x; X[a][1]=v0.y; X[a][2]=v0.z; X[a][3]=v0.w;
        X[a][4]=v1.x; X[a][5]=v1.y; X[a][6]=v1.z; X[a][7]=v1.w;
    }
    float tmp[8][8];
    #pragma unroll
    for (int a = 0; a < 8; a++) {
        #pragma unroll
        for (int n = 0; n < 8; n++) {
            float s = 0.f;
            #pragma unroll
            for (int bq = 0; bq < 8; bq++) s += X[a][bq] * M[n*8+bq];
            tmp[a][n] = s;
        }
    }
    float* op = out + (size_t)bc*HW + ph*8*Ww + pw*8;
    #pragma unroll
    for (int m = 0; m < 8; m++) {
        float y[8];
        #pragma unroll
        for (int n = 0; n < 8; n++) {
            float s = 0.f;
            #pragma unroll
            for (int a = 0; a < 8; a++) s += M[m*8+a] * tmp[a][n];
            y[n] = s;
        }
        *(float4*)(op + m*Ww)     = make_float4(y[0], y[1], y[2], y[3]);
        *(float4*)(op + m*Ww + 4) = make_float4(y[4], y[5], y[6], y[7]);
    }
}

// ------------------- Gram matrices S[bh][c][d] = <qf_c, kf_d> -------------
__global__ void k_dot(const float* __restrict__ qf, const float* __restrict__ kf)
{
    int bh = blockIdx.y; int b = bh >> 2, h = bh & 3;
    const float* qb = qf + ((size_t)b*64 + h*16)*LLEN;
    const float* kb = kf + ((size_t)b*64 + h*16)*LLEN;
    int tid = threadIdx.x;
    int c = tid >> 4, d = tid & 15;
    __shared__ float qs[16][65], ks[16][65];
    float acc = 0.f;
    int l0 = blockIdx.x * 4096;
    for (int lt = 0; lt < 4096; lt += 64) {
        int base = l0 + lt;
        for (int t = tid; t < 1024; t += 256) {
            int r = t >> 6, i = t & 63;
            qs[r][i] = qb[(size_t)r*LLEN + base + i];
            ks[r][i] = kb[(size_t)r*LLEN + base + i];
        }
        __syncthreads();
        #pragma unroll
        for (int i = 0; i < 64; i++) acc += qs[c][i] * ks[d][i];
        __syncthreads();
    }
    atomicAdd(&g_S[bh*256 + tid], acc);
}

// ------------------- finalize logits + softmax over d ---------------------
__global__ void k_softmax(const float* __restrict__ temp)
{
    int bh = blockIdx.x; int b = bh >> 2, h = bh & 3;
    int tid = threadIdx.x; int c = tid >> 4, d = tid & 15;
    float nq = fmaxf(sqrtf(g_sqq[b*64 + h*16 + c]), 1e-12f);
    float nk = fmaxf(sqrtf(g_sqk[b*64 + h*16 + d]), 1e-12f);
    float logit = g_S[bh*256 + tid] / (nq*nk) * temp[h];
    float mx = logit;
    #pragma unroll
    for (int off = 8; off; off >>= 1)
        mx = fmaxf(mx, __shfl_xor_sync(0xffffffffu, mx, off, 16));
    float e = expf(logit - mx);
    float s = e;
    #pragma unroll
    for (int off = 8; off; off >>= 1)
        s += __shfl_xor_sync(0xffffffffu, s, off, 16);
    g_attn[bh*256 + tid] = e / s;
}

// ------------------- o[c][l] = sum_d attn[c][d]*out1[d][l] ----------------
__global__ void k_apply(const float* __restrict__ out1, float* __restrict__ o)
{
    int bh = blockIdx.y; int b = bh >> 2, h = bh & 3;
    __shared__ float as_[256];
    as_[threadIdx.x] = g_attn[bh*256 + threadIdx.x];
    __syncthreads();
    int l = blockIdx.x*256 + threadIdx.x;
    size_t base = ((size_t)b*64 + h*16)*LLEN + l;
    float xv[16];
    #pragma unroll
    for (int dd = 0; dd < 16; dd++) xv[dd] = out1[base + (size_t)dd*LLEN];
    #pragma unroll
    for (int cc = 0; cc < 16; cc++) {
        float acc = 0.f;
        #pragma unroll
        for (int dd = 0; dd < 16; dd++) acc += as_[cc*16 + dd] * xv[dd];
        o[base + (size_t)cc*LLEN] = acc;
    }
}

// ------------------- fused: t1/t2 + dw3 + prelu, both pool branches -------
// u1 = prelu(dw3(q*out, w1a), a1); u2 = prelu(dw3(v - lam*(v*out), w2a), a2)
__global__ void __launch_bounds__(256) k_poolA(
    const float* __restrict__ q, const float* __restrict__ o,
    const float* __restrict__ kv,
    const float* __restrict__ w1a, const float* __restrict__ w2a,
    const float* __restrict__ a1p, const float* __restrict__ a2p,
    float* __restrict__ u1, float* __restrict__ u2)
{
    int g = blockIdx.x*256 + threadIdx.x;
    int px = g*4;
    int x = px % Ww;
    int y = (px / Ww) % Hh;
    int bc = px / HW;
    int ch = bc & 63;
    int b = bc >> 6;
    const float* qp = q + (size_t)bc*HW;
    const float* op = o + (size_t)bc*HW;
    const float* vp = kv + ((size_t)b*128 + 64 + ch)*HW;
    float lam = g_lam;
    float w1[9], w2[9];
    #pragma unroll
    for (int i = 0; i < 9; i++) { w1[i] = __ldg(w1a + ch*9 + i); w2[i] = __ldg(w2a + ch*9 + i); }
    float acc1[4] = {0,0,0,0}, acc2[4] = {0,0,0,0};
    #pragma unroll
    for (int dy = -1; dy <= 1; dy++) {
        int yy = y + dy;
        if ((unsigned)yy < (unsigned)Hh) {
            float qv[6], ov[6], vv[6];
            load6(qp + yy*Ww, x, qv);
            load6(op + yy*Ww, x, ov);
            load6(vp + yy*Ww, x, vv);
            float t1[6], t2[6];
            #pragma unroll
            for (int m = 0; m < 6; m++) {
                t1[m] = qv[m] * ov[m];
                t2[m] = vv[m] - lam * (vv[m] * ov[m]);
            }
            const float* r1 = w1 + (dy+1)*3;
            const float* r2 = w2 + (dy+1)*3;
            #pragma unroll
            for (int j = 0; j < 4; j++) {
                acc1[j] += r1[0]*t1[j] + r1[1]*t1[j+1] + r1[2]*t1[j+2];
                acc2[j] += r2[0]*t2[j] + r2[1]*t2[j+1] + r2[2]*t2[j+2];
            }
        }
    }
    float a1 = *a1p, a2 = *a2p;
    float4 r1, r2;
    r1.x = acc1[0] >= 0.f ? acc1[0] : a1*acc1[0];
    r1.y = acc1[1] >= 0.f ? acc1[1] : a1*acc1[1];
    r1.z = acc1[2] >= 0.f ? acc1[2] : a1*acc1[2];
    r1.w = acc1[3] >= 0.f ? acc1[3] : a1*acc1[3];
    r2.x = acc2[0] >= 0.f ? acc2[0] : a2*acc2[0];
    r2.y = acc2[1] >= 0.f ? acc2[1] : a2*acc2[1];
    r2.z = acc2[2] >= 0.f ? acc2[2] : a2*acc2[2];
    r2.w = acc2[3] >= 0.f ? acc2[3] : a2*acc2[3];
    *(float4*)(u1 + px) = r1;
    *(float4*)(u2 + px) = r2;
}

// ------------------- fused: out = dw3(u1,w1b) + dw3(u2,w2b) ---------------
__global__ void __launch_bounds__(256) k_poolB(
    const float* __restrict__ u1, const float* __restrict__ u2,
    const float* __restrict__ w1b, const float* __restrict__ w2b,
    float* __restrict__ out)
{
    int g = blockIdx.x*256 + threadIdx.x;
    int px = g*4;
    int x = px % Ww;
    int y = (px / Ww) % Hh;
    int bc = px / HW;
    int ch = bc & 63;
    const float* p1 = u1 + (size_t)bc*HW;
    const float* p2 = u2 + (size_t)bc*HW;
    float w1[9], w2[9];
    #pragma unroll
    for (int i = 0; i < 9; i++) { w1[i] = __ldg(w1b + ch*9 + i); w2[i] = __ldg(w2b + ch*9 + i); }
    float acc[4] = {0,0,0,0};
    #pragma unroll
    for (int dy = -1; dy <= 1; dy++) {
        int yy = y + dy;
        if ((unsigned)yy < (unsigned)Hh) {
            float v1[6], v2[6];
            load6(p1 + yy*Ww, x, v1);
            load6(p2 + yy*Ww, x, v2);
            const float* r1 = w1 + (dy+1)*3;
            const float* r2 = w2 + (dy+1)*3;
            #pragma unroll
            for (int j = 0; j < 4; j++) {
                acc[j] += r1[0]*v1[j] + r1[1]*v1[j+1] + r1[2]*v1[j+2]
                        + r2[0]*v2[j] + r2[1]*v2[j+1] + r2[2]*v2[j+2];
            }
        }
    }
    *(float4*)(out + px) = make_float4(acc[0], acc[1], acc[2], acc[3]);
}

// ------------------- host launcher ----------------------------------------
extern "C" void kernel_launch(void* const* d_in, const int* in_sizes, int n_in,
                              void* d_out, int out_size)
{
    const float* x            = (const float*)d_in[0];
    const float* nir          = (const float*)d_in[1];
    const float* w_hidden     = (const float*)d_in[2];
    const float* w_hidden_nir = (const float*)d_in[3];
    const float* w_dw         = (const float*)d_in[4];
    const float* w_dw_nir     = (const float*)d_in[5];
    const float* temperature  = (const float*)d_in[6];
    const float* w_proj_mid   = (const float*)d_in[7];
    const float* w_proj_out   = (const float*)d_in[8];
    const float* w_p1a        = (const float*)d_in[9];
    const float* a_p1         = (const float*)d_in[10];
    const float* w_p1b        = (const float*)d_in[11];
    const float* w_p2a        = (const float*)d_in[12];
    const float* a_p2         = (const float*)d_in[13];
    const float* w_p2b        = (const float*)d_in[14];
    const float* lq1          = (const float*)d_in[15];
    const float* lk1          = (const float*)d_in[16];
    const float* lq2          = (const float*)d_in[17];
    const float* lk2          = (const float*)d_in[18];

    float *A, *Bf, *Cf, *D, *E, *F, *G;
    cudaGetSymbolAddress((void**)&A,  g_bA);
    cudaGetSymbolAddress((void**)&Bf, g_bB);
    cudaGetSymbolAddress((void**)&Cf, g_bC);
    cudaGetSymbolAddress((void**)&D,  g_bD);
    cudaGetSymbolAddress((void**)&E,  g_bE);
    cudaGetSymbolAddress((void**)&F,  g_bF);
    cudaGetSymbolAddress((void**)&G,  g_bG);

    k_init<<<1, 64>>>(lq1, lk1, lq2, lk2);

    // hidden = W_h @ x ; nir_hidden = W_hn @ nir
    k_conv1x1<<<dim3(HW/512, Bb, 1), 256>>>(x,   w_hidden,     A,  64);
    k_conv1x1<<<dim3(HW/512, Bb, 2), 256>>>(nir, w_hidden_nir, Bf, 128);

    // q = dw3(hidden) ; kv = dw3(nir_hidden)
    k_dw3v<<<NTOT/1024,   256>>>(A,  w_dw,     Cf, 63);
    k_dw3v<<<2*NTOT/1024, 256>>>(Bf, w_dw_nir, D,  127);

    // DCTs (fused: qf+sumsq; kf+out1+sumsq)
    k_dctq<<<NPATCH/128, 128>>>(Cf, E);
    k_dctk<<<NPATCH/128, 128>>>(D, E, F, G);

    // attention
    k_dot<<<dim3(36, 8), 256>>>(E, F);
    k_softmax<<<8, 256>>>(temperature);
    k_apply<<<dim3(LLEN/256, 8), 256>>>(G, E);   // o_freq into E

    // idct -> spatial o (F); out = W_pm @ o (A)
    k_idct<<<NPATCH/128, 128>>>(E, F);
    k_conv1x1<<<dim3(HW/512, Bb, 1), 256>>>(F, w_proj_mid, A, 64);

    // fused pools
    k_poolA<<<NTOT/1024, 256>>>(Cf, A, D, w_p1a, w_p2a, a_p1, a_p2, E, F);
    k_poolB<<<NTOT/1024, 256>>>(E, F, w_p1b, w_p2b, G);

    // final projection
    k_conv1x1<<<dim3(HW/512, Bb, 1), 256>>>(G, w_proj_out, (float*)d_out, 64);
}

// round 3
// speedup vs baseline: 1.4110x; 1.0549x over previous
#include <cuda_runtime.h>
#include <math.h>

#define Bb 2
#define Cc 64
#define Hh 384
#define Ww 384
#define HW (Hh*Ww)            // 147456
#define NTOT (Bb*Cc*HW)       // 18874368
#define HH 48
#define WW 48
#define LLEN HW               // 147456
#define NPATCH (Bb*Cc*HH*WW)  // 294912

typedef unsigned long long ull;

// ------------------- scratch (device globals) -----------------------------
__device__ float g_bA[NTOT];      // hidden -> out(proj_mid)
__device__ float g_bB[2*NTOT];    // nir_hidden
__device__ float g_bC[NTOT];      // q
__device__ float g_bD[2*NTOT];    // kv
__device__ float g_bE[NTOT];      // qf -> o_spatial -> pooled
__device__ float g_bF[NTOT];      // kf -> u1
__device__ float g_bG[NTOT];      // out1 -> u2

__device__ float g_DCTM[64];      // [a*8+m]
__device__ float g_IDCTM[64];     // [m*8+a]
__device__ float g_sqq[128];
__device__ float g_sqk[128];
__device__ float g_S[8*256];
__device__ float g_attn[8*256];
__device__ float g_lam;

// ------------------- packed f32x2 helpers (sm_100+) -----------------------
__device__ __forceinline__ ull pk2(float lo, float hi) {
    ull r; asm("mov.b64 %0, {%1,%2};" : "=l"(r) : "f"(lo), "f"(hi)); return r;
}
__device__ __forceinline__ void upk2(float& lo, float& hi, ull v) {
    asm("mov.b64 {%0,%1}, %2;" : "=f"(lo), "=f"(hi) : "l"(v));
}
#define FMA2(d, a, b, c) asm("fma.rn.f32x2 %0, %1, %2, %3;" : "=l"(d) : "l"(a), "l"(b), "l"(c))

// ------------------- init ---------------------------------------------------
__global__ void k_init(const float* __restrict__ lq1, const float* __restrict__ lk1,
                       const float* __restrict__ lq2, const float* __restrict__ lk2)
{
    int t = threadIdx.x;  // 64 threads
    if (t < 64) {
        int a = t >> 3, m = t & 7;
        double cv = 2.0 * cos(3.14159265358979323846 * (double)((2*m+1)*a) / 16.0);
        g_DCTM[a*8+m] = (float)cv;
        g_IDCTM[m*8+a] = (float)(cv / (a == 0 ? 32.0 : 16.0));
    }
    if (t < 32) {
        float s1 = lq1[t]*lk1[t] + lq1[t+32]*lk1[t+32];
        float s2 = lq2[t]*lk2[t] + lq2[t+32]*lk2[t+32];
        #pragma unroll
        for (int off = 16; off; off >>= 1) {
            s1 += __shfl_xor_sync(0xffffffffu, s1, off);
            s2 += __shfl_xor_sync(0xffffffffu, s2, off);
        }
        if (t == 0) {
            float lam_init = 0.8f - 0.6f * (float)exp(-1.8);
            g_lam = expf(s1) - expf(s2) + lam_init;
        }
    }
    for (int i = t; i < 2048; i += 64) g_S[i] = 0.f;
    for (int i = t; i < 128;  i += 64) { g_sqq[i] = 0.f; g_sqk[i] = 0.f; }
}

// ------------------- conv1x1, packed FFMA2, 16oc x 4px per thread ---------
// block 256 thr: group g=tid>>6 covers oc [g*16, g*16+16); (tid&63)*4 pixels.
// grid = (HW/256, B, OCtot/64). ~100 regs -> 2 blocks/SM.
__global__ void __launch_bounds__(256) k_conv1x1(
    const float* __restrict__ in, const float* __restrict__ w,
    float* __restrict__ out, int OCtot)
{
    __shared__ ull ws[64*64];     // (w,w) packed, [oc][ic], 32KB
    int ocBase = blockIdx.z * 64;
    int b = blockIdx.y;
    int tid = threadIdx.x;
    for (int t = tid; t < 4096; t += 256) {
        int j = t >> 6, i = t & 63;
        float wv = w[(ocBase + j)*64 + i];
        ws[t] = pk2(wv, wv);
    }
    __syncthreads();
    const float* inb = in + (size_t)b*64*HW;
    int g = tid >> 6;                       // oc group 0..3
    int p0 = blockIdx.x*256 + (tid & 63)*4;
    ull accA[16], accB[16];
    #pragma unroll
    for (int j = 0; j < 16; j++) { accA[j] = 0ULL; accB[j] = 0ULL; }
    const ull* wrow = ws + g*16*64;
    #pragma unroll 4
    for (int i = 0; i < 64; i++) {
        float4 xv = *(const float4*)(inb + (size_t)i*HW + p0);
        ull xA = pk2(xv.x, xv.y);
        ull xB = pk2(xv.z, xv.w);
        #pragma unroll
        for (int j = 0; j < 16; j++) {
            ull wv = wrow[j*64 + i];
            FMA2(accA[j], wv, xA, accA[j]);
            FMA2(accB[j], wv, xB, accB[j]);
        }
    }
    float* outb = out + ((size_t)b*OCtot + ocBase + g*16)*HW;
    #pragma unroll
    for (int j = 0; j < 16; j++) {
        float o0, o1, o2, o3;
        upk2(o0, o1, accA[j]);
        upk2(o2, o3, accB[j]);
        *(float4*)(outb + (size_t)j*HW + p0) = make_float4(o0, o1, o2, o3);
    }
}

// ------------------- row loader: 6 values around aligned 4-px group -------
__device__ __forceinline__ void load6(const float* __restrict__ row, int x, float v[6])
{
    float4 c = *(const float4*)(row + x);
    v[1] = c.x; v[2] = c.y; v[3] = c.z; v[4] = c.w;
    v[0] = (x > 0)      ? row[x-1] : 0.f;
    v[5] = (x+4 < Ww)   ? row[x+4] : 0.f;
}

// ------------------- depthwise 3x3, 4 px/thread ---------------------------
__global__ void __launch_bounds__(256) k_dw3v(
    const float* __restrict__ in, const float* __restrict__ w9,
    float* __restrict__ out, int chMask)
{
    int g = blockIdx.x*256 + threadIdx.x;
    int px = g*4;
    int x = px % Ww;
    int y = (px / Ww) % Hh;
    int bc = px / HW;
    int ch = bc & chMask;
    const float* ip = in + (size_t)bc*HW;
    float w[9];
    #pragma unroll
    for (int i = 0; i < 9; i++) w[i] = __ldg(w9 + ch*9 + i);
    float acc[4] = {0.f, 0.f, 0.f, 0.f};
    #pragma unroll
    for (int dy = -1; dy <= 1; dy++) {
        int yy = y + dy;
        if ((unsigned)yy < (unsigned)Hh) {
            float v[6];
            load6(ip + yy*Ww, x, v);
            const float* wr = w + (dy+1)*3;
            #pragma unroll
            for (int j = 0; j < 4; j++)
                acc[j] += wr[0]*v[j] + wr[1]*v[j+1] + wr[2]*v[j+2];
        }
    }
    *(float4*)(out + px) = make_float4(acc[0], acc[1], acc[2], acc[3]);
}

// ------------------- DCT(q): write qf, accumulate sumsq -------------------
__global__ void k_dctq(const float* __restrict__ in, float* __restrict__ qf)
{
    __shared__ float M[64];
    __shared__ float red[4];
    if (threadIdx.x < 64) M[threadIdx.x] = g_DCTM[threadIdx.x];
    __syncthreads();
    int p = blockIdx.x*128 + threadIdx.x;
    int pw = p % WW;
    int t2 = p / WW;
    int ph = t2 % HH;
    int bc = t2 / HH;
    const float* ip = in + (size_t)bc*HW + ph*8*Ww + pw*8;
    float tmp[8][8];
    #pragma unroll
    for (int m = 0; m < 8; m++) {
        float4 v0 = *(const float4*)(ip + m*Ww);
        float4 v1 = *(const float4*)(ip + m*Ww + 4);
        float r[8] = {v0.x, v0.y, v0.z, v0.w, v1.x, v1.y, v1.z, v1.w};
        #pragma unroll
        for (int bb = 0; bb < 8; bb++) {
            float s = 0.f;
            #pragma unroll
            for (int n = 0; n < 8; n++) s += r[n] * M[bb*8+n];
            tmp[m][bb] = s;
        }
    }
    float* op = qf + (size_t)p*64;
    float ss = 0.f;
    #pragma unroll
    for (int a = 0; a < 8; a++) {
        float y[8];
        #pragma unroll
        for (int bb = 0; bb < 8; bb++) {
            float s = 0.f;
            #pragma unroll
            for (int m = 0; m < 8; m++) s += M[a*8+m] * tmp[m][bb];
            y[bb] = s;
            ss += s*s;
        }
        *(float4*)(op + a*8)     = make_float4(y[0], y[1], y[2], y[3]);
        *(float4*)(op + a*8 + 4) = make_float4(y[4], y[5], y[6], y[7]);
    }
    #pragma unroll
    for (int off = 16; off; off >>= 1) ss += __shfl_xor_sync(0xffffffffu, ss, off);
    if ((threadIdx.x & 31) == 0) red[threadIdx.x >> 5] = ss;
    __syncthreads();
    if (threadIdx.x == 0)
        atomicAdd(&g_sqq[bc], red[0]+red[1]+red[2]+red[3]);
}

// ------------------- DCT(k): write kf, out1 = qf*kf, sumsq ----------------
__global__ void k_dctk(const float* __restrict__ kv, const float* __restrict__ qf,
                       float* __restrict__ kf, float* __restrict__ out1)
{
    __shared__ float M[64];
    __shared__ float red[4];
    if (threadIdx.x < 64) M[threadIdx.x] = g_DCTM[threadIdx.x];
    __syncthreads();
    int p = blockIdx.x*128 + threadIdx.x;
    int pw = p % WW;
    int t2 = p / WW;
    int ph = t2 % HH;
    int bc = t2 / HH;
    int b = bc >> 6, ch = bc & 63;
    const float* ip = kv + ((size_t)b*128 + ch)*HW + ph*8*Ww + pw*8;
    float tmp[8][8];
    #pragma unroll
    for (int m = 0; m < 8; m++) {
        float4 v0 = *(const float4*)(ip + m*Ww);
        float4 v1 = *(const float4*)(ip + m*Ww + 4);
        float r[8] = {v0.x, v0.y, v0.z, v0.w, v1.x, v1.y, v1.z, v1.w};
        #pragma unroll
        for (int bb = 0; bb < 8; bb++) {
            float s = 0.f;
            #pragma unroll
            for (int n = 0; n < 8; n++) s += r[n] * M[bb*8+n];
            tmp[m][bb] = s;
        }
    }
    float* kp = kf + (size_t)p*64;
    float* o1 = out1 + (size_t)p*64;
    const float* qp = qf + (size_t)p*64;
    float ss = 0.f;
    #pragma unroll
    for (int a = 0; a < 8; a++) {
        float y[8];
        #pragma unroll
        for (int bb = 0; bb < 8; bb++) {
            float s = 0.f;
            #pragma unroll
            for (int m = 0; m < 8; m++) s += M[a*8+m] * tmp[m][bb];
            y[bb] = s;
            ss += s*s;
        }
        float4 q0 = *(const float4*)(qp + a*8);
        float4 q1 = *(const float4*)(qp + a*8 + 4);
        *(float4*)(kp + a*8)     = make_float4(y[0], y[1], y[2], y[3]);
        *(float4*)(kp + a*8 + 4) = make_float4(y[4], y[5], y[6], y[7]);
        *(float4*)(o1 + a*8)     = make_float4(q0.x*y[0], q0.y*y[1], q0.z*y[2], q0.w*y[3]);
        *(float4*)(o1 + a*8 + 4) = make_float4(q1.x*y[4], q1.y*y[5], q1.z*y[6], q1.w*y[7]);
    }
    #pragma unroll
    for (int off = 16; off; off >>= 1) ss += __shfl_xor_sync(0xffffffffu, ss, off);
    if ((threadIdx.x & 31) == 0) red[threadIdx.x >> 5] = ss;
    __syncthreads();
    if (threadIdx.x == 0)
        atomicAdd(&g_sqk[bc], red[0]+red[1]+red[2]+red[3]);
}

// ------------------- Gram matrices S[bh][c][d] = <qf_c, kf_d> -------------
__global__ void k_dot(const float* __restrict__ qf, const float* __restrict__ kf)
{
    int bh = blockIdx.y; int b = bh >> 2, h = bh & 3;
    const float* qb = qf + ((size_t)b*64 + h*16)*LLEN;
    const float* kb = kf + ((size_t)b*64 + h*16)*LLEN;
    int tid = threadIdx.x;
    int c = tid >> 4, d = tid & 15;
    __shared__ float qs[16][65], ks[16][65];
    float acc = 0.f;
    int l0 = blockIdx.x * 4096;
    for (int lt = 0; lt < 4096; lt += 64) {
        int base = l0 + lt;
        for (int t = tid; t < 1024; t += 256) {
            int r = t >> 6, i = t & 63;
            qs[r][i] = qb[(size_t)r*LLEN + base + i];
            ks[r][i] = kb[(size_t)r*LLEN + base + i];
        }
        __syncthreads();
        #pragma unroll
        for (int i = 0; i < 64; i++) acc += qs[c][i] * ks[d][i];
        __syncthreads();
    }
    atomicAdd(&g_S[bh*256 + tid], acc);
}

// ------------------- finalize logits + softmax over d ---------------------
__global__ void k_softmax(const float* __restrict__ temp)
{
    int bh = blockIdx.x; int b = bh >> 2, h = bh & 3;
    int tid = threadIdx.x; int c = tid >> 4, d = tid & 15;
    float nq = fmaxf(sqrtf(g_sqq[b*64 + h*16 + c]), 1e-12f);
    float nk = fmaxf(sqrtf(g_sqk[b*64 + h*16 + d]), 1e-12f);
    float logit = g_S[bh*256 + tid] / (nq*nk) * temp[h];
    float mx = logit;
    #pragma unroll
    for (int off = 8; off; off >>= 1)
        mx = fmaxf(mx, __shfl_xor_sync(0xffffffffu, mx, off, 16));
    float e = expf(logit - mx);
    float s = e;
    #pragma unroll
    for (int off = 8; off; off >>= 1)
        s += __shfl_xor_sync(0xffffffffu, s, off, 16);
    g_attn[bh*256 + tid] = e / s;
}

// ------------------- fused attention-apply + IDCT -------------------------
// block: 128 thr, 8 patch-positions x 16 head-channels.
// grid (2304/8=288, 8 bh). smem-stages 16 out1 rows for 8 positions.
#define SMP 1028   // padded stride per patch (floats)
__global__ void __launch_bounds__(128) k_applyidct(
    const float* __restrict__ out1, float* __restrict__ out)
{
    __shared__ float sm[8*SMP];
    __shared__ float at[256];
    __shared__ float M[64];
    int bh = blockIdx.y; int b = bh >> 2, h = bh & 3;
    int tid = threadIdx.x;
    if (tid < 64) M[tid] = g_IDCTM[tid];
    at[tid]       = g_attn[bh*256 + tid];
    at[tid + 128] = g_attn[bh*256 + tid + 128];
    int pos0 = blockIdx.x * 8;
    int pp_l = tid >> 4;
    int ab_l = (tid & 15) * 4;
    #pragma unroll 4
    for (int d = 0; d < 16; d++) {
        const float* src = out1 + (((size_t)(b*64 + h*16 + d))*2304 + pos0)*64;
        float4 v = *(const float4*)(src + tid*4);
        *(float4*)(sm + pp_l*SMP + d*64 + ab_l) = v;
    }
    __syncthreads();

    int pp = tid >> 4, cd = tid & 15;
    const float* arow = at + cd*16;
    float X[64];
    #pragma unroll
    for (int i = 0; i < 64; i++) X[i] = 0.f;
    #pragma unroll
    for (int d = 0; d < 16; d++) {
        float av = arow[d];
        const float4* s4 = (const float4*)(sm + pp*SMP + d*64);
        #pragma unroll
        for (int q4 = 0; q4 < 16; q4++) {
            float4 v = s4[q4];
            X[q4*4+0] += av * v.x;
            X[q4*4+1] += av * v.y;
            X[q4*4+2] += av * v.z;
            X[q4*4+3] += av * v.w;
        }
    }
    // IDCT: Y = Ci X Ci^T using M[m*8+a]
    float tmp[8][8];
    #pragma unroll
    for (int a = 0; a < 8; a++) {
        #pragma unroll
        for (int n = 0; n < 8; n++) {
            float s = 0.f;
            #pragma unroll
            for (int bq = 0; bq < 8; bq++) s += X[a*8+bq] * M[n*8+bq];
            tmp[a][n] = s;
        }
    }
    int pos = pos0 + pp;
    int ph = pos / WW, pw = pos % WW;
    int bc = b*64 + h*16 + cd;
    float* op = out + (size_t)bc*HW + ph*8*Ww + pw*8;
    #pragma unroll
    for (int m = 0; m < 8; m++) {
        float y[8];
        #pragma unroll
        for (int n = 0; n < 8; n++) {
            float s = 0.f;
            #pragma unroll
            for (int a = 0; a < 8; a++) s += M[m*8+a] * tmp[a][n];
            y[n] = s;
        }
        *(float4*)(op + m*Ww)     = make_float4(y[0], y[1], y[2], y[3]);
        *(float4*)(op + m*Ww + 4) = make_float4(y[4], y[5], y[6], y[7]);
    }
}

// ------------------- fused: t1/t2 + dw3 + prelu, both pool branches -------
__global__ void __launch_bounds__(256) k_poolA(
    const float* __restrict__ q, const float* __restrict__ o,
    const float* __restrict__ kv,
    const float* __restrict__ w1a, const float* __restrict__ w2a,
    const float* __restrict__ a1p, const float* __restrict__ a2p,
    float* __restrict__ u1, float* __restrict__ u2)
{
    int g = blockIdx.x*256 + threadIdx.x;
    int px = g*4;
    int x = px % Ww;
    int y = (px / Ww) % Hh;
    int bc = px / HW;
    int ch = bc & 63;
    int b = bc >> 6;
    const float* qp = q + (size_t)bc*HW;
    const float* op = o + (size_t)bc*HW;
    const float* vp = kv + ((size_t)b*128 + 64 + ch)*HW;
    float lam = g_lam;
    float w1[9], w2[9];
    #pragma unroll
    for (int i = 0; i < 9; i++) { w1[i] = __ldg(w1a + ch*9 + i); w2[i] = __ldg(w2a + ch*9 + i); }
    float acc1[4] = {0,0,0,0}, acc2[4] = {0,0,0,0};
    #pragma unroll
    for (int dy = -1; dy <= 1; dy++) {
        int yy = y + dy;
        if ((unsigned)yy < (unsigned)Hh) {
            float qv[6], ov[6], vv[6];
            load6(qp + yy*Ww, x, qv);
            load6(op + yy*Ww, x, ov);
            load6(vp + yy*Ww, x, vv);
            float t1[6], t2[6];
            #pragma unroll
            for (int m = 0; m < 6; m++) {
                t1[m] = qv[m] * ov[m];
                t2[m] = vv[m] - lam * (vv[m] * ov[m]);
            }
            const float* r1 = w1 + (dy+1)*3;
            const float* r2 = w2 + (dy+1)*3;
            #pragma unroll
            for (int j = 0; j < 4; j++) {
                acc1[j] += r1[0]*t1[j] + r1[1]*t1[j+1] + r1[2]*t1[j+2];
                acc2[j] += r2[0]*t2[j] + r2[1]*t2[j+1] + r2[2]*t2[j+2];
            }
        }
    }
    float a1 = *a1p, a2 = *a2p;
    float4 r1, r2;
    r1.x = acc1[0] >= 0.f ? acc1[0] : a1*acc1[0];
    r1.y = acc1[1] >= 0.f ? acc1[1] : a1*acc1[1];
    r1.z = acc1[2] >= 0.f ? acc1[2] : a1*acc1[2];
    r1.w = acc1[3] >= 0.f ? acc1[3] : a1*acc1[3];
    r2.x = acc2[0] >= 0.f ? acc2[0] : a2*acc2[0];
    r2.y = acc2[1] >= 0.f ? acc2[1] : a2*acc2[1];
    r2.z = acc2[2] >= 0.f ? acc2[2] : a2*acc2[2];
    r2.w = acc2[3] >= 0.f ? acc2[3] : a2*acc2[3];
    *(float4*)(u1 + px) = r1;
    *(float4*)(u2 + px) = r2;
}

// ------------------- fused: out = dw3(u1,w1b) + dw3(u2,w2b) ---------------
__global__ void __launch_bounds__(256) k_poolB(
    const float* __restrict__ u1, const float* __restrict__ u2,
    const float* __restrict__ w1b, const float* __restrict__ w2b,
    float* __restrict__ out)
{
    int g = blockIdx.x*256 + threadIdx.x;
    int px = g*4;
    int x = px % Ww;
    int y = (px / Ww) % Hh;
    int bc = px / HW;
    int ch = bc & 63;
    const float* p1 = u1 + (size_t)bc*HW;
    const float* p2 = u2 + (size_t)bc*HW;
    float w1[9], w2[9];
    #pragma unroll
    for (int i = 0; i < 9; i++) { w1[i] = __ldg(w1b + ch*9 + i); w2[i] = __ldg(w2b + ch*9 + i); }
    float acc[4] = {0,0,0,0};
    #pragma unroll
    for (int dy = -1; dy <= 1; dy++) {
        int yy = y + dy;
        if ((unsigned)yy < (unsigned)Hh) {
            float v1[6], v2[6];
            load6(p1 + yy*Ww, x, v1);
            load6(p2 + yy*Ww, x, v2);
            const float* r1 = w1 + (dy+1)*3;
            const float* r2 = w2 + (dy+1)*3;
            #pragma unroll
            for (int j = 0; j < 4; j++) {
                acc[j] += r1[0]*v1[j] + r1[1]*v1[j+1] + r1[2]*v1[j+2]
                        + r2[0]*v2[j] + r2[1]*v2[j+1] + r2[2]*v2[j+2];
            }
        }
    }
    *(float4*)(out + px) = make_float4(acc[0], acc[1], acc[2], acc[3]);
}

// ------------------- host launcher ----------------------------------------
extern "C" void kernel_launch(void* const* d_in, const int* in_sizes, int n_in,
                              void* d_out, int out_size)
{
    const float* x            = (const float*)d_in[0];
    const float* nir          = (const float*)d_in[1];
    const float* w_hidden     = (const float*)d_in[2];
    const float* w_hidden_nir = (const float*)d_in[3];
    const float* w_dw         = (const float*)d_in[4];
    const float* w_dw_nir     = (const float*)d_in[5];
    const float* temperature  = (const float*)d_in[6];
    const float* w_proj_mid   = (const float*)d_in[7];
    const float* w_proj_out   = (const float*)d_in[8];
    const float* w_p1a        = (const float*)d_in[9];
    const float* a_p1         = (const float*)d_in[10];
    const float* w_p1b        = (const float*)d_in[11];
    const float* w_p2a        = (const float*)d_in[12];
    const float* a_p2         = (const float*)d_in[13];
    const float* w_p2b        = (const float*)d_in[14];
    const float* lq1          = (const float*)d_in[15];
    const float* lk1          = (const float*)d_in[16];
    const float* lq2          = (const float*)d_in[17];
    const float* lk2          = (const float*)d_in[18];

    float *A, *Bf, *Cf, *D, *E, *F, *G;
    cudaGetSymbolAddress((void**)&A,  g_bA);
    cudaGetSymbolAddress((void**)&Bf, g_bB);
    cudaGetSymbolAddress((void**)&Cf, g_bC);
    cudaGetSymbolAddress((void**)&D,  g_bD);
    cudaGetSymbolAddress((void**)&E,  g_bE);
    cudaGetSymbolAddress((void**)&F,  g_bF);
    cudaGetSymbolAddress((void**)&G,  g_bG);

    k_init<<<1, 64>>>(lq1, lk1, lq2, lk2);

    // hidden = W_h @ x ; nir_hidden = W_hn @ nir
    k_conv1x1<<<dim3(HW/256, Bb, 1), 256>>>(x,   w_hidden,     A,  64);
    k_conv1x1<<<dim3(HW/256, Bb, 2), 256>>>(nir, w_hidden_nir, Bf, 128);

    // q = dw3(hidden) ; kv = dw3(nir_hidden)
    k_dw3v<<<NTOT/1024,   256>>>(A,  w_dw,     Cf, 63);
    k_dw3v<<<2*NTOT/1024, 256>>>(Bf, w_dw_nir, D,  127);

    // DCTs (fused: qf+sumsq; kf+out1+sumsq)
    k_dctq<<<NPATCH/128, 128>>>(Cf, E);
    k_dctk<<<NPATCH/128, 128>>>(D, E, F, G);

    // attention: Gram -> softmax -> fused apply+IDCT (o_spatial into E)
    k_dot<<<dim3(36, 8), 256>>>(E, F);
    k_softmax<<<8, 256>>>(temperature);
    k_applyidct<<<dim3(HH*WW/8, 8), 128>>>(G, E);

    // out = W_pm @ o
    k_conv1x1<<<dim3(HW/256, Bb, 1), 256>>>(E, w_proj_mid, A, 64);

    // fused pools
    k_poolA<<<NTOT/1024, 256>>>(Cf, A, D, w_p1a, w_p2a, a_p1, a_p2, F, G);
    k_poolB<<<NTOT/1024, 256>>>(F, G, w_p1b, w_p2b, E);

    // final projection
    k_conv1x1<<<dim3(HW/256, Bb, 1), 256>>>(E, w_proj_out, (float*)d_out, 64);
}

// round 4
// speedup vs baseline: 1.8666x; 1.3229x over previous
#include <cuda_runtime.h>
#include <math.h>

#define Bb 2
#define Cc 64
#define Hh 384
#define Ww 384
#define HW (Hh*Ww)            // 147456
#define NTOT (Bb*Cc*HW)       // 18874368
#define HH 48
#define WW 48
#define LLEN HW               // 147456
#define NPATCH (Bb*Cc*HH*WW)  // 294912

typedef unsigned long long ull;

// ------------------- scratch (device globals) -----------------------------
__device__ float g_bA[NTOT];      // hidden -> out(proj_mid)
__device__ float g_bB[2*NTOT];    // nir_hidden
__device__ float g_bC[NTOT];      // q
__device__ float g_bD[2*NTOT];    // kv
__device__ float g_bE[NTOT];      // qf -> o_spatial -> pooled
__device__ float g_bF[NTOT];      // kf -> u1
__device__ float g_bG[NTOT];      // out1 -> u2

__device__ float g_DCTM[64];      // [a*8+m]
__device__ float g_IDCTM[64];     // [m*8+a]
__device__ float g_sqq[128];
__device__ float g_sqk[128];
__device__ float g_S[8*256];
__device__ float g_attn[8*256];
__device__ float g_lam;

// ------------------- packed f32x2 helpers (sm_100+) -----------------------
__device__ __forceinline__ ull pk2(float lo, float hi) {
    ull r; asm("mov.b64 %0, {%1,%2};" : "=l"(r) : "f"(lo), "f"(hi)); return r;
}
#define FMA2(d, a, b, c) asm("fma.rn.f32x2 %0, %1, %2, %3;" : "=l"(d) : "l"(a), "l"(b), "l"(c))

// ------------------- init ---------------------------------------------------
__global__ void k_init(const float* __restrict__ lq1, const float* __restrict__ lk1,
                       const float* __restrict__ lq2, const float* __restrict__ lk2)
{
    int t = threadIdx.x;  // 64 threads
    if (t < 64) {
        int a = t >> 3, m = t & 7;
        double cv = 2.0 * cos(3.14159265358979323846 * (double)((2*m+1)*a) / 16.0);
        g_DCTM[a*8+m] = (float)cv;
        g_IDCTM[m*8+a] = (float)(cv / (a == 0 ? 32.0 : 16.0));
    }
    if (t < 32) {
        float s1 = lq1[t]*lk1[t] + lq1[t+32]*lk1[t+32];
        float s2 = lq2[t]*lk2[t] + lq2[t+32]*lk2[t+32];
        #pragma unroll
        for (int off = 16; off; off >>= 1) {
            s1 += __shfl_xor_sync(0xffffffffu, s1, off);
            s2 += __shfl_xor_sync(0xffffffffu, s2, off);
        }
        if (t == 0) {
            float lam_init = 0.8f - 0.6f * (float)exp(-1.8);
            g_lam = expf(s1) - expf(s2) + lam_init;
        }
    }
    for (int i = t; i < 2048; i += 64) g_S[i] = 0.f;
    for (int i = t; i < 128;  i += 64) { g_sqq[i] = 0.f; g_sqk[i] = 0.f; }
}

// ------------------- conv1x1 as smem-tiled GEMM (FFMA2) -------------------
// Tile per block: 64 oc x 128 px, k=64. 256 threads: og=tid>>5 (8 oc each),
// (tid&31)*4 pixels each. Input tile + packed weights staged in 64KB smem.
// Per k-step: 8 broadcast LDS.64 + 1 LDS.128 + 16 FFMA2 -> fma-pipe bound.
__global__ void __launch_bounds__(256) k_conv1x1(
    const float* __restrict__ in, const float* __restrict__ w,
    float* __restrict__ out, int OCtot)
{
    extern __shared__ char smraw[];
    ull*   ws = (ull*)smraw;                  // [64 oc][64 ic] (w,w)  32KB
    float* xs = (float*)(smraw + 32768);      // [64 ic][128 px]       32KB
    int ocBase = blockIdx.z * 64;
    int b = blockIdx.y;
    int tid = threadIdx.x;

    // stage packed weights: t = j*64+i  ->  w[(ocBase+j)*64+i]
    #pragma unroll
    for (int r = 0; r < 16; r++) {
        int t = r*256 + tid;
        ws[t] = pk2(__ldg(w + ocBase*64 + t), __ldg(w + ocBase*64 + t));
    }
    // stage input tile, coalesced
    const float* inb = in + (size_t)b*64*HW + blockIdx.x*128;
    {
        int icr = tid >> 5;
        int px  = (tid & 31) * 4;
        #pragma unroll
        for (int r = 0; r < 8; r++) {
            int ic = r*8 + icr;
            *(float4*)(xs + ic*128 + px) = *(const float4*)(inb + (size_t)ic*HW + px);
        }
    }
    __syncthreads();

    int og = tid >> 5;                 // oc group (warp-uniform)
    const ull* wbase = ws + og*8*64;
    const float* xrow = xs + (tid & 31)*4;
    ull acc[8][2];
    #pragma unroll
    for (int j = 0; j < 8; j++) { acc[j][0] = 0ULL; acc[j][1] = 0ULL; }

    #pragma unroll 4
    for (int k = 0; k < 64; k++) {
        ulonglong2 px = *(const ulonglong2*)(xrow + k*128);   // (p0,p1),(p2,p3)
        #pragma unroll
        for (int j = 0; j < 8; j++) {
            ull wv = wbase[j*64 + k];
            FMA2(acc[j][0], wv, px.x, acc[j][0]);
            FMA2(acc[j][1], wv, px.y, acc[j][1]);
        }
    }

    float* outb = out + ((size_t)b*OCtot + ocBase + og*8)*HW
                + blockIdx.x*128 + (tid & 31)*4;
    #pragma unroll
    for (int j = 0; j < 8; j++) {
        ulonglong2 v; v.x = acc[j][0]; v.y = acc[j][1];
        *(ulonglong2*)(outb + (size_t)j*HW) = v;
    }
}

// ------------------- row loader: 6 values around aligned 4-px group -------
__device__ __forceinline__ void load6(const float* __restrict__ row, int x, float v[6])
{
    float4 c = *(const float4*)(row + x);
    v[1] = c.x; v[2] = c.y; v[3] = c.z; v[4] = c.w;
    v[0] = (x > 0)      ? row[x-1] : 0.f;
    v[5] = (x+4 < Ww)   ? row[x+4] : 0.f;
}

// ------------------- depthwise 3x3, 4 px/thread ---------------------------
__global__ void __launch_bounds__(256) k_dw3v(
    const float* __restrict__ in, const float* __restrict__ w9,
    float* __restrict__ out, int chMask)
{
    int g = blockIdx.x*256 + threadIdx.x;
    int px = g*4;
    int x = px % Ww;
    int y = (px / Ww) % Hh;
    int bc = px / HW;
    int ch = bc & chMask;
    const float* ip = in + (size_t)bc*HW;
    float w[9];
    #pragma unroll
    for (int i = 0; i < 9; i++) w[i] = __ldg(w9 + ch*9 + i);
    float acc[4] = {0.f, 0.f, 0.f, 0.f};
    #pragma unroll
    for (int dy = -1; dy <= 1; dy++) {
        int yy = y + dy;
        if ((unsigned)yy < (unsigned)Hh) {
            float v[6];
            load6(ip + yy*Ww, x, v);
            const float* wr = w + (dy+1)*3;
            #pragma unroll
            for (int j = 0; j < 4; j++)
                acc[j] += wr[0]*v[j] + wr[1]*v[j+1] + wr[2]*v[j+2];
        }
    }
    *(float4*)(out + px) = make_float4(acc[0], acc[1], acc[2], acc[3]);
}

// ------------------- DCT(q): write qf, accumulate sumsq -------------------
__global__ void k_dctq(const float* __restrict__ in, float* __restrict__ qf)
{
    __shared__ float M[64];
    __shared__ float red[4];
    if (threadIdx.x < 64) M[threadIdx.x] = g_DCTM[threadIdx.x];
    __syncthreads();
    int p = blockIdx.x*128 + threadIdx.x;
    int pw = p % WW;
    int t2 = p / WW;
    int ph = t2 % HH;
    int bc = t2 / HH;
    const float* ip = in + (size_t)bc*HW + ph*8*Ww + pw*8;
    float tmp[8][8];
    #pragma unroll
    for (int m = 0; m < 8; m++) {
        float4 v0 = *(const float4*)(ip + m*Ww);
        float4 v1 = *(const float4*)(ip + m*Ww + 4);
        float r[8] = {v0.x, v0.y, v0.z, v0.w, v1.x, v1.y, v1.z, v1.w};
        #pragma unroll
        for (int bb = 0; bb < 8; bb++) {
            float s = 0.f;
            #pragma unroll
            for (int n = 0; n < 8; n++) s += r[n] * M[bb*8+n];
            tmp[m][bb] = s;
        }
    }
    float* op = qf + (size_t)p*64;
    float ss = 0.f;
    #pragma unroll
    for (int a = 0; a < 8; a++) {
        float y[8];
        #pragma unroll
        for (int bb = 0; bb < 8; bb++) {
            float s = 0.f;
            #pragma unroll
            for (int m = 0; m < 8; m++) s += M[a*8+m] * tmp[m][bb];
            y[bb] = s;
            ss += s*s;
        }
        *(float4*)(op + a*8)     = make_float4(y[0], y[1], y[2], y[3]);
        *(float4*)(op + a*8 + 4) = make_float4(y[4], y[5], y[6], y[7]);
    }
    #pragma unroll
    for (int off = 16; off; off >>= 1) ss += __shfl_xor_sync(0xffffffffu, ss, off);
    if ((threadIdx.x & 31) == 0) red[threadIdx.x >> 5] = ss;
    __syncthreads();
    if (threadIdx.x == 0)
        atomicAdd(&g_sqq[bc], red[0]+red[1]+red[2]+red[3]);
}

// ------------------- DCT(k): write kf, out1 = qf*kf, sumsq ----------------
__global__ void k_dctk(const float* __restrict__ kv, const float* __restrict__ qf,
                       float* __restrict__ kf, float* __restrict__ out1)
{
    __shared__ float M[64];
    __shared__ float red[4];
    if (threadIdx.x < 64) M[threadIdx.x] = g_DCTM[threadIdx.x];
    __syncthreads();
    int p = blockIdx.x*128 + threadIdx.x;
    int pw = p % WW;
    int t2 = p / WW;
    int ph = t2 % HH;
    int bc = t2 / HH;
    int b = bc >> 6, ch = bc & 63;
    const float* ip = kv + ((size_t)b*128 + ch)*HW + ph*8*Ww + pw*8;
    float tmp[8][8];
    #pragma unroll
    for (int m = 0; m < 8; m++) {
        float4 v0 = *(const float4*)(ip + m*Ww);
        float4 v1 = *(const float4*)(ip + m*Ww + 4);
        float r[8] = {v0.x, v0.y, v0.z, v0.w, v1.x, v1.y, v1.z, v1.w};
        #pragma unroll
        for (int bb = 0; bb < 8; bb++) {
            float s = 0.f;
            #pragma unroll
            for (int n = 0; n < 8; n++) s += r[n] * M[bb*8+n];
            tmp[m][bb] = s;
        }
    }
    float* kp = kf + (size_t)p*64;
    float* o1 = out1 + (size_t)p*64;
    const float* qp = qf + (size_t)p*64;
    float ss = 0.f;
    #pragma unroll
    for (int a = 0; a < 8; a++) {
        float y[8];
        #pragma unroll
        for (int bb = 0; bb < 8; bb++) {
            float s = 0.f;
            #pragma unroll
            for (int m = 0; m < 8; m++) s += M[a*8+m] * tmp[m][bb];
            y[bb] = s;
            ss += s*s;
        }
        float4 q0 = *(const float4*)(qp + a*8);
        float4 q1 = *(const float4*)(qp + a*8 + 4);
        *(float4*)(kp + a*8)     = make_float4(y[0], y[1], y[2], y[3]);
        *(float4*)(kp + a*8 + 4) = make_float4(y[4], y[5], y[6], y[7]);
        *(float4*)(o1 + a*8)     = make_float4(q0.x*y[0], q0.y*y[1], q0.z*y[2], q0.w*y[3]);
        *(float4*)(o1 + a*8 + 4) = make_float4(q1.x*y[4], q1.y*y[5], q1.z*y[6], q1.w*y[7]);
    }
    #pragma unroll
    for (int off = 16; off; off >>= 1) ss += __shfl_xor_sync(0xffffffffu, ss, off);
    if ((threadIdx.x & 31) == 0) red[threadIdx.x >> 5] = ss;
    __syncthreads();
    if (threadIdx.x == 0)
        atomicAdd(&g_sqk[bc], red[0]+red[1]+red[2]+red[3]);
}

// ------------------- Gram matrices S[bh][c][d] = <qf_c, kf_d> -------------
__global__ void k_dot(const float* __restrict__ qf, const float* __restrict__ kf)
{
    int bh = blockIdx.y; int b = bh >> 2, h = bh & 3;
    const float* qb = qf + ((size_t)b*64 + h*16)*LLEN;
    const float* kb = kf + ((size_t)b*64 + h*16)*LLEN;
    int tid = threadIdx.x;
    int c = tid >> 4, d = tid & 15;
    __shared__ float qs[16][65], ks[16][65];
    float acc = 0.f;
    int l0 = blockIdx.x * 4096;
    for (int lt = 0; lt < 4096; lt += 64) {
        int base = l0 + lt;
        for (int t = tid; t < 1024; t += 256) {
            int r = t >> 6, i = t & 63;
            qs[r][i] = qb[(size_t)r*LLEN + base + i];
            ks[r][i] = kb[(size_t)r*LLEN + base + i];
        }
        __syncthreads();
        #pragma unroll
        for (int i = 0; i < 64; i++) acc += qs[c][i] * ks[d][i];
        __syncthreads();
    }
    atomicAdd(&g_S[bh*256 + tid], acc);
}

// ------------------- finalize logits + softmax over d ---------------------
__global__ void k_softmax(const float* __restrict__ temp)
{
    int bh = blockIdx.x; int b = bh >> 2, h = bh & 3;
    int tid = threadIdx.x; int c = tid >> 4, d = tid & 15;
    float nq = fmaxf(sqrtf(g_sqq[b*64 + h*16 + c]), 1e-12f);
    float nk = fmaxf(sqrtf(g_sqk[b*64 + h*16 + d]), 1e-12f);
    float logit = g_S[bh*256 + tid] / (nq*nk) * temp[h];
    float mx = logit;
    #pragma unroll
    for (int off = 8; off; off >>= 1)
        mx = fmaxf(mx, __shfl_xor_sync(0xffffffffu, mx, off, 16));
    float e = expf(logit - mx);
    float s = e;
    #pragma unroll
    for (int off = 8; off; off >>= 1)
        s += __shfl_xor_sync(0xffffffffu, s, off, 16);
    g_attn[bh*256 + tid] = e / s;
}

// ------------------- fused attention-apply + IDCT -------------------------
#define SMP 1028   // padded stride per patch (floats)
__global__ void __launch_bounds__(128) k_applyidct(
    const float* __restrict__ out1, float* __restrict__ out)
{
    __shared__ float sm[8*SMP];
    __shared__ float at[256];
    __shared__ float M[64];
    int bh = blockIdx.y; int b = bh >> 2, h = bh & 3;
    int tid = threadIdx.x;
    if (tid < 64) M[tid] = g_IDCTM[tid];
    at[tid]       = g_attn[bh*256 + tid];
    at[tid + 128] = g_attn[bh*256 + tid + 128];
    int pos0 = blockIdx.x * 8;
    int pp_l = tid >> 4;
    int ab_l = (tid & 15) * 4;
    #pragma unroll 4
    for (int d = 0; d < 16; d++) {
        const float* src = out1 + (((size_t)(b*64 + h*16 + d))*2304 + pos0)*64;
        float4 v = *(const float4*)(src + tid*4);
        *(float4*)(sm + pp_l*SMP + d*64 + ab_l) = v;
    }
    __syncthreads();

    int pp = tid >> 4, cd = tid & 15;
    const float* arow = at + cd*16;
    float X[64];
    #pragma unroll
    for (int i = 0; i < 64; i++) X[i] = 0.f;
    #pragma unroll
    for (int d = 0; d < 16; d++) {
        float av = arow[d];
        const float4* s4 = (const float4*)(sm + pp*SMP + d*64);
        #pragma unroll
        for (int q4 = 0; q4 < 16; q4++) {
            float4 v = s4[q4];
            X[q4*4+0] += av * v.x;
            X[q4*4+1] += av * v.y;
            X[q4*4+2] += av * v.z;
            X[q4*4+3] += av * v.w;
        }
    }
    float tmp[8][8];
    #pragma unroll
    for (int a = 0; a < 8; a++) {
        #pragma unroll
        for (int n = 0; n < 8; n++) {
            float s = 0.f;
            #pragma unroll
            for (int bq = 0; bq < 8; bq++) s += X[a*8+bq] * M[n*8+bq];
            tmp[a][n] = s;
        }
    }
    int pos = pos0 + pp;
    int ph = pos / WW, pw = pos % WW;
    int bc = b*64 + h*16 + cd;
    float* op = out + (size_t)bc*HW + ph*8*Ww + pw*8;
    #pragma unroll
    for (int m = 0; m < 8; m++) {
        float y[8];
        #pragma unroll
        for (int n = 0; n < 8; n++) {
            float s = 0.f;
            #pragma unroll
            for (int a = 0; a < 8; a++) s += M[m*8+a] * tmp[a][n];
            y[n] = s;
        }
        *(float4*)(op + m*Ww)     = make_float4(y[0], y[1], y[2], y[3]);
        *(float4*)(op + m*Ww + 4) = make_float4(y[4], y[5], y[6], y[7]);
    }
}

// ------------------- fused: t1/t2 + dw3 + prelu, both pool branches -------
__global__ void __launch_bounds__(256) k_poolA(
    const float* __restrict__ q, const float* __restrict__ o,
    const float* __restrict__ kv,
    const float* __restrict__ w1a, const float* __restrict__ w2a,
    const float* __restrict__ a1p, const float* __restrict__ a2p,
    float* __restrict__ u1, float* __restrict__ u2)
{
    int g = blockIdx.x*256 + threadIdx.x;
    int px = g*4;
    int x = px % Ww;
    int y = (px / Ww) % Hh;
    int bc = px / HW;
    int ch = bc & 63;
    int b = bc >> 6;
    const float* qp = q + (size_t)bc*HW;
    const float* op = o + (size_t)bc*HW;
    const float* vp = kv + ((size_t)b*128 + 64 + ch)*HW;
    float lam = g_lam;
    float w1[9], w2[9];
    #pragma unroll
    for (int i = 0; i < 9; i++) { w1[i] = __ldg(w1a + ch*9 + i); w2[i] = __ldg(w2a + ch*9 + i); }
    float acc1[4] = {0,0,0,0}, acc2[4] = {0,0,0,0};
    #pragma unroll
    for (int dy = -1; dy <= 1; dy++) {
        int yy = y + dy;
        if ((unsigned)yy < (unsigned)Hh) {
            float qv[6], ov[6], vv[6];
            load6(qp + yy*Ww, x, qv);
            load6(op + yy*Ww, x, ov);
            load6(vp + yy*Ww, x, vv);
            float t1[6], t2[6];
            #pragma unroll
            for (int m = 0; m < 6; m++) {
                t1[m] = qv[m] * ov[m];
                t2[m] = vv[m] - lam * (vv[m] * ov[m]);
            }
            const float* r1 = w1 + (dy+1)*3;
            const float* r2 = w2 + (dy+1)*3;
            #pragma unroll
            for (int j = 0; j < 4; j++) {
                acc1[j] += r1[0]*t1[j] + r1[1]*t1[j+1] + r1[2]*t1[j+2];
                acc2[j] += r2[0]*t2[j] + r2[1]*t2[j+1] + r2[2]*t2[j+2];
            }
        }
    }
    float a1 = *a1p, a2 = *a2p;
    float4 r1, r2;
    r1.x = acc1[0] >= 0.f ? acc1[0] : a1*acc1[0];
    r1.y = acc1[1] >= 0.f ? acc1[1] : a1*acc1[1];
    r1.z = acc1[2] >= 0.f ? acc1[2] : a1*acc1[2];
    r1.w = acc1[3] >= 0.f ? acc1[3] : a1*acc1[3];
    r2.x = acc2[0] >= 0.f ? acc2[0] : a2*acc2[0];
    r2.y = acc2[1] >= 0.f ? acc2[1] : a2*acc2[1];
    r2.z = acc2[2] >= 0.f ? acc2[2] : a2*acc2[2];
    r2.w = acc2[3] >= 0.f ? acc2[3] : a2*acc2[3];
    *(float4*)(u1 + px) = r1;
    *(float4*)(u2 + px) = r2;
}

// ------------------- fused: out = dw3(u1,w1b) + dw3(u2,w2b) ---------------
__global__ void __launch_bounds__(256) k_poolB(
    const float* __restrict__ u1, const float* __restrict__ u2,
    const float* __restrict__ w1b, const float* __restrict__ w2b,
    float* __restrict__ out)
{
    int g = blockIdx.x*256 + threadIdx.x;
    int px = g*4;
    int x = px % Ww;
    int y = (px / Ww) % Hh;
    int bc = px / HW;
    int ch = bc & 63;
    const float* p1 = u1 + (size_t)bc*HW;
    const float* p2 = u2 + (size_t)bc*HW;
    float w1[9], w2[9];
    #pragma unroll
    for (int i = 0; i < 9; i++) { w1[i] = __ldg(w1b + ch*9 + i); w2[i] = __ldg(w2b + ch*9 + i); }
    float acc[4] = {0,0,0,0};
    #pragma unroll
    for (int dy = -1; dy <= 1; dy++) {
        int yy = y + dy;
        if ((unsigned)yy < (unsigned)Hh) {
            float v1[6], v2[6];
            load6(p1 + yy*Ww, x, v1);
            load6(p2 + yy*Ww, x, v2);
            const float* r1 = w1 + (dy+1)*3;
            const float* r2 = w2 + (dy+1)*3;
            #pragma unroll
            for (int j = 0; j < 4; j++) {
                acc[j] += r1[0]*v1[j] + r1[1]*v1[j+1] + r1[2]*v1[j+2]
                        + r2[0]*v2[j] + r2[1]*v2[j+1] + r2[2]*v2[j+2];
            }
        }
    }
    *(float4*)(out + px) = make_float4(acc[0], acc[1], acc[2], acc[3]);
}

// ------------------- host launcher ----------------------------------------
extern "C" void kernel_launch(void* const* d_in, const int* in_sizes, int n_in,
                              void* d_out, int out_size)
{
    const float* x            = (const float*)d_in[0];
    const float* nir          = (const float*)d_in[1];
    const float* w_hidden     = (const float*)d_in[2];
    const float* w_hidden_nir = (const float*)d_in[3];
    const float* w_dw         = (const float*)d_in[4];
    const float* w_dw_nir     = (const float*)d_in[5];
    const float* temperature  = (const float*)d_in[6];
    const float* w_proj_mid   = (const float*)d_in[7];
    const float* w_proj_out   = (const float*)d_in[8];
    const float* w_p1a        = (const float*)d_in[9];
    const float* a_p1         = (const float*)d_in[10];
    const float* w_p1b        = (const float*)d_in[11];
    const float* w_p2a        = (const float*)d_in[12];
    const float* a_p2         = (const float*)d_in[13];
    const float* w_p2b        = (const float*)d_in[14];
    const float* lq1          = (const float*)d_in[15];
    const float* lk1          = (const float*)d_in[16];
    const float* lq2          = (const float*)d_in[17];
    const float* lk2          = (const float*)d_in[18];

    float *A, *Bf, *Cf, *D, *E, *F, *G;
    cudaGetSymbolAddress((void**)&A,  g_bA);
    cudaGetSymbolAddress((void**)&Bf, g_bB);
    cudaGetSymbolAddress((void**)&Cf, g_bC);
    cudaGetSymbolAddress((void**)&D,  g_bD);
    cudaGetSymbolAddress((void**)&E,  g_bE);
    cudaGetSymbolAddress((void**)&F,  g_bF);
    cudaGetSymbolAddress((void**)&G,  g_bG);

    const int CONV_SMEM = 65536;
    cudaFuncSetAttribute(k_conv1x1, cudaFuncAttributeMaxDynamicSharedMemorySize, CONV_SMEM);

    k_init<<<1, 64>>>(lq1, lk1, lq2, lk2);

    // hidden = W_h @ x ; nir_hidden = W_hn @ nir
    k_conv1x1<<<dim3(HW/128, Bb, 1), 256, CONV_SMEM>>>(x,   w_hidden,     A,  64);
    k_conv1x1<<<dim3(HW/128, Bb, 2), 256, CONV_SMEM>>>(nir, w_hidden_nir, Bf, 128);

    // q = dw3(hidden) ; kv = dw3(nir_hidden)
    k_dw3v<<<NTOT/1024,   256>>>(A,  w_dw,     Cf, 63);
    k_dw3v<<<2*NTOT/1024, 256>>>(Bf, w_dw_nir, D,  127);

    // DCTs (fused: qf+sumsq; kf+out1+sumsq)
    k_dctq<<<NPATCH/128, 128>>>(Cf, E);
    k_dctk<<<NPATCH/128, 128>>>(D, E, F, G);

    // attention: Gram -> softmax -> fused apply+IDCT (o_spatial into E)
    k_dot<<<dim3(36, 8), 256>>>(E, F);
    k_softmax<<<8, 256>>>(temperature);
    k_applyidct<<<dim3(HH*WW/8, 8), 128>>>(G, E);

    // out = W_pm @ o
    k_conv1x1<<<dim3(HW/128, Bb, 1), 256, CONV_SMEM>>>(E, w_proj_mid, A, 64);

    // fused pools
    k_poolA<<<NTOT/1024, 256>>>(Cf, A, D, w_p1a, w_p2a, a_p1, a_p2, F, G);
    k_poolB<<<NTOT/1024, 256>>>(F, G, w_p1b, w_p2b, E);

    // final projection
    k_conv1x1<<<dim3(HW/128, Bb, 1), 256, CONV_SMEM>>>(E, w_proj_out, (float*)d_out, 64);
}

// round 5
// speedup vs baseline: 1.8948x; 1.0151x over previous
#include <cuda_runtime.h>
#include <math.h>

#define Bb 2
#define Cc 64
#define Hh 384
#define Ww 384
#define HW (Hh*Ww)            // 147456
#define NTOT (Bb*Cc*HW)       // 18874368
#define HH 48
#define WW 48
#define LLEN HW               // 147456
#define NPATCH (Bb*Cc*HH*WW)  // 294912

typedef unsigned long long ull;

// ------------------- scratch (device globals) -----------------------------
__device__ float g_bA[NTOT];      // hidden -> o_spatial's conv out
__device__ float g_bB[2*NTOT];    // nir_hidden
__device__ float g_bC[NTOT];      // q
__device__ float g_bD[2*NTOT];    // kv
__device__ float g_bE[NTOT];      // qf -> o_spatial
__device__ float g_bF[NTOT];      // kf
__device__ float g_bG[NTOT];      // out1 -> pooled output

__device__ float g_DCTM[64];      // [a*8+m]
__device__ float g_IDCTM[64];     // [m*8+a]
__device__ float g_sqq[128];
__device__ float g_sqk[128];
__device__ float g_S[8*256];
__device__ float g_attn[8*256];
__device__ float g_lam;

// ------------------- packed f32x2 helpers (sm_100+) -----------------------
__device__ __forceinline__ ull pk2(float lo, float hi) {
    ull r; asm("mov.b64 %0, {%1,%2};" : "=l"(r) : "f"(lo), "f"(hi)); return r;
}
#define FMA2(d, a, b, c) asm("fma.rn.f32x2 %0, %1, %2, %3;" : "=l"(d) : "l"(a), "l"(b), "l"(c))

// ------------------- init ---------------------------------------------------
__global__ void k_init(const float* __restrict__ lq1, const float* __restrict__ lk1,
                       const float* __restrict__ lq2, const float* __restrict__ lk2)
{
    int t = threadIdx.x;  // 64 threads
    if (t < 64) {
        int a = t >> 3, m = t & 7;
        double cv = 2.0 * cos(3.14159265358979323846 * (double)((2*m+1)*a) / 16.0);
        g_DCTM[a*8+m] = (float)cv;
        g_IDCTM[m*8+a] = (float)(cv / (a == 0 ? 32.0 : 16.0));
    }
    if (t < 32) {
        float s1 = lq1[t]*lk1[t] + lq1[t+32]*lk1[t+32];
        float s2 = lq2[t]*lk2[t] + lq2[t+32]*lk2[t+32];
        #pragma unroll
        for (int off = 16; off; off >>= 1) {
            s1 += __shfl_xor_sync(0xffffffffu, s1, off);
            s2 += __shfl_xor_sync(0xffffffffu, s2, off);
        }
        if (t == 0) {
            float lam_init = 0.8f - 0.6f * (float)exp(-1.8);
            g_lam = expf(s1) - expf(s2) + lam_init;
        }
    }
    for (int i = t; i < 2048; i += 64) g_S[i] = 0.f;
    for (int i = t; i < 128;  i += 64) { g_sqq[i] = 0.f; g_sqk[i] = 0.f; }
}

// ------------------- conv1x1 as smem-tiled GEMM (FFMA2) -------------------
// Block tile: 64 oc x 256 px, k=64. 256 threads: ocg=tid>>4 -> 4 oc each,
// pxg=tid&15 -> 16 px each (4 strided groups of 4 consecutive px).
// Per k-step per thread: 4 weight LDS.64 (broadcast) + 4 LDS.128 + 32 FFMA2
// -> fma-pipe bound (crossbar ~12 cyc vs 64 fma cyc per warp-k).
__global__ void __launch_bounds__(256) k_conv1x1(
    const float* __restrict__ in, const float* __restrict__ w,
    float* __restrict__ out, int OCtot)
{
    extern __shared__ char smraw[];
    ull*   ws = (ull*)smraw;                  // [64 oc][64 ic] (w,w)  32KB
    float* xs = (float*)(smraw + 32768);      // [64 ic][256 px]       64KB
    int ocBase = blockIdx.z * 64;
    int b = blockIdx.y;
    int tid = threadIdx.x;

    #pragma unroll
    for (int r = 0; r < 16; r++) {
        int t = r*256 + tid;
        float wv = __ldg(w + ocBase*64 + t);
        ws[t] = pk2(wv, wv);
    }
    const float* inb = in + (size_t)b*64*HW + blockIdx.x*256;
    #pragma unroll
    for (int r = 0; r < 16; r++) {
        int idx = r*256 + tid;        // 0..4095 float4 slots
        int ic  = idx >> 6;
        int c4  = (idx & 63) * 4;
        *(float4*)(xs + ic*256 + c4) = *(const float4*)(inb + (size_t)ic*HW + c4);
    }
    __syncthreads();

    int ocg = tid >> 4;               // 0..15 -> 4 oc
    int pxg = tid & 15;               // 0..15
    int oc0 = ocg * 4;
    int px0 = pxg * 4;                // + 64*t, t=0..3

    ull acc[4][8];
    #pragma unroll
    for (int j = 0; j < 4; j++)
        #pragma unroll
        for (int t = 0; t < 8; t++) acc[j][t] = 0ULL;

    const ull* wbase = ws + oc0*64;
    #pragma unroll 4
    for (int k = 0; k < 64; k++) {
        const float* xr = xs + k*256 + px0;
        ulonglong2 p0 = *(const ulonglong2*)(xr);
        ulonglong2 p1 = *(const ulonglong2*)(xr + 64);
        ulonglong2 p2 = *(const ulonglong2*)(xr + 128);
        ulonglong2 p3 = *(const ulonglong2*)(xr + 192);
        #pragma unroll
        for (int j = 0; j < 4; j++) {
            ull wv = wbase[j*64 + k];
            FMA2(acc[j][0], wv, p0.x, acc[j][0]);
            FMA2(acc[j][1], wv, p0.y, acc[j][1]);
            FMA2(acc[j][2], wv, p1.x, acc[j][2]);
            FMA2(acc[j][3], wv, p1.y, acc[j][3]);
            FMA2(acc[j][4], wv, p2.x, acc[j][4]);
            FMA2(acc[j][5], wv, p2.y, acc[j][5]);
            FMA2(acc[j][6], wv, p3.x, acc[j][6]);
            FMA2(acc[j][7], wv, p3.y, acc[j][7]);
        }
    }

    float* outb = out + ((size_t)b*OCtot + ocBase + oc0)*HW + blockIdx.x*256 + px0;
    #pragma unroll
    for (int j = 0; j < 4; j++) {
        #pragma unroll
        for (int t = 0; t < 4; t++) {
            ulonglong2 v; v.x = acc[j][t*2]; v.y = acc[j][t*2+1];
            *(ulonglong2*)(outb + (size_t)j*HW + t*64) = v;
        }
    }
}

// ------------------- row loader: 6 values around aligned 4-px group -------
__device__ __forceinline__ void load6(const float* __restrict__ row, int x, float v[6])
{
    float4 c = *(const float4*)(row + x);
    v[1] = c.x; v[2] = c.y; v[3] = c.z; v[4] = c.w;
    v[0] = (x > 0)      ? row[x-1] : 0.f;
    v[5] = (x+4 < Ww)   ? row[x+4] : 0.f;
}

// ------------------- depthwise 3x3, 4 px/thread ---------------------------
__global__ void __launch_bounds__(256) k_dw3v(
    const float* __restrict__ in, const float* __restrict__ w9,
    float* __restrict__ out, int chMask)
{
    int g = blockIdx.x*256 + threadIdx.x;
    int px = g*4;
    int x = px % Ww;
    int y = (px / Ww) % Hh;
    int bc = px / HW;
    int ch = bc & chMask;
    const float* ip = in + (size_t)bc*HW;
    float w[9];
    #pragma unroll
    for (int i = 0; i < 9; i++) w[i] = __ldg(w9 + ch*9 + i);
    float acc[4] = {0.f, 0.f, 0.f, 0.f};
    #pragma unroll
    for (int dy = -1; dy <= 1; dy++) {
        int yy = y + dy;
        if ((unsigned)yy < (unsigned)Hh) {
            float v[6];
            load6(ip + yy*Ww, x, v);
            const float* wr = w + (dy+1)*3;
            #pragma unroll
            for (int j = 0; j < 4; j++)
                acc[j] += wr[0]*v[j] + wr[1]*v[j+1] + wr[2]*v[j+2];
        }
    }
    *(float4*)(out + px) = make_float4(acc[0], acc[1], acc[2], acc[3]);
}

// ------------------- DCT(q): write qf, accumulate sumsq -------------------
__global__ void k_dctq(const float* __restrict__ in, float* __restrict__ qf)
{
    __shared__ float M[64];
    __shared__ float red[4];
    if (threadIdx.x < 64) M[threadIdx.x] = g_DCTM[threadIdx.x];
    __syncthreads();
    int p = blockIdx.x*128 + threadIdx.x;
    int pw = p % WW;
    int t2 = p / WW;
    int ph = t2 % HH;
    int bc = t2 / HH;
    const float* ip = in + (size_t)bc*HW + ph*8*Ww + pw*8;
    float tmp[8][8];
    #pragma unroll
    for (int m = 0; m < 8; m++) {
        float4 v0 = *(const float4*)(ip + m*Ww);
        float4 v1 = *(const float4*)(ip + m*Ww + 4);
        float r[8] = {v0.x, v0.y, v0.z, v0.w, v1.x, v1.y, v1.z, v1.w};
        #pragma unroll
        for (int bb = 0; bb < 8; bb++) {
            float s = 0.f;
            #pragma unroll
            for (int n = 0; n < 8; n++) s += r[n] * M[bb*8+n];
            tmp[m][bb] = s;
        }
    }
    float* op = qf + (size_t)p*64;
    float ss = 0.f;
    #pragma unroll
    for (int a = 0; a < 8; a++) {
        float y[8];
        #pragma unroll
        for (int bb = 0; bb < 8; bb++) {
            float s = 0.f;
            #pragma unroll
            for (int m = 0; m < 8; m++) s += M[a*8+m] * tmp[m][bb];
            y[bb] = s;
            ss += s*s;
        }
        *(float4*)(op + a*8)     = make_float4(y[0], y[1], y[2], y[3]);
        *(float4*)(op + a*8 + 4) = make_float4(y[4], y[5], y[6], y[7]);
    }
    #pragma unroll
    for (int off = 16; off; off >>= 1) ss += __shfl_xor_sync(0xffffffffu, ss, off);
    if ((threadIdx.x & 31) == 0) red[threadIdx.x >> 5] = ss;
    __syncthreads();
    if (threadIdx.x == 0)
        atomicAdd(&g_sqq[bc], red[0]+red[1]+red[2]+red[3]);
}

// ------------------- DCT(k): write kf, out1 = qf*kf, sumsq ----------------
__global__ void k_dctk(const float* __restrict__ kv, const float* __restrict__ qf,
                       float* __restrict__ kf, float* __restrict__ out1)
{
    __shared__ float M[64];
    __shared__ float red[4];
    if (threadIdx.x < 64) M[threadIdx.x] = g_DCTM[threadIdx.x];
    __syncthreads();
    int p = blockIdx.x*128 + threadIdx.x;
    int pw = p % WW;
    int t2 = p / WW;
    int ph = t2 % HH;
    int bc = t2 / HH;
    int b = bc >> 6, ch = bc & 63;
    const float* ip = kv + ((size_t)b*128 + ch)*HW + ph*8*Ww + pw*8;
    float tmp[8][8];
    #pragma unroll
    for (int m = 0; m < 8; m++) {
        float4 v0 = *(const float4*)(ip + m*Ww);
        float4 v1 = *(const float4*)(ip + m*Ww + 4);
        float r[8] = {v0.x, v0.y, v0.z, v0.w, v1.x, v1.y, v1.z, v1.w};
        #pragma unroll
        for (int bb = 0; bb < 8; bb++) {
            float s = 0.f;
            #pragma unroll
            for (int n = 0; n < 8; n++) s += r[n] * M[bb*8+n];
            tmp[m][bb] = s;
        }
    }
    float* kp = kf + (size_t)p*64;
    float* o1 = out1 + (size_t)p*64;
    const float* qp = qf + (size_t)p*64;
    float ss = 0.f;
    #pragma unroll
    for (int a = 0; a < 8; a++) {
        float y[8];
        #pragma unroll
        for (int bb = 0; bb < 8; bb++) {
            float s = 0.f;
            #pragma unroll
            for (int m = 0; m < 8; m++) s += M[a*8+m] * tmp[m][bb];
            y[bb] = s;
            ss += s*s;
        }
        float4 q0 = *(const float4*)(qp + a*8);
        float4 q1 = *(const float4*)(qp + a*8 + 4);
        *(float4*)(kp + a*8)     = make_float4(y[0], y[1], y[2], y[3]);
        *(float4*)(kp + a*8 + 4) = make_float4(y[4], y[5], y[6], y[7]);
        *(float4*)(o1 + a*8)     = make_float4(q0.x*y[0], q0.y*y[1], q0.z*y[2], q0.w*y[3]);
        *(float4*)(o1 + a*8 + 4) = make_float4(q1.x*y[4], q1.y*y[5], q1.z*y[6], q1.w*y[7]);
    }
    #pragma unroll
    for (int off = 16; off; off >>= 1) ss += __shfl_xor_sync(0xffffffffu, ss, off);
    if ((threadIdx.x & 31) == 0) red[threadIdx.x >> 5] = ss;
    __syncthreads();
    if (threadIdx.x == 0)
        atomicAdd(&g_sqk[bc], red[0]+red[1]+red[2]+red[3]);
}

// ------------------- Gram matrices S[bh][c][d] = <qf_c, kf_d> -------------
__global__ void k_dot(const float* __restrict__ qf, const float* __restrict__ kf)
{
    int bh = blockIdx.y; int b = bh >> 2, h = bh & 3;
    const float* qb = qf + ((size_t)b*64 + h*16)*LLEN;
    const float* kb = kf + ((size_t)b*64 + h*16)*LLEN;
    int tid = threadIdx.x;
    int c = tid >> 4, d = tid & 15;
    __shared__ float qs[16][65], ks[16][65];
    float acc = 0.f;
    int l0 = blockIdx.x * 4096;
    for (int lt = 0; lt < 4096; lt += 64) {
        int base = l0 + lt;
        for (int t = tid; t < 1024; t += 256) {
            int r = t >> 6, i = t & 63;
            qs[r][i] = qb[(size_t)r*LLEN + base + i];
            ks[r][i] = kb[(size_t)r*LLEN + base + i];
        }
        __syncthreads();
        #pragma unroll
        for (int i = 0; i < 64; i++) acc += qs[c][i] * ks[d][i];
        __syncthreads();
    }
    atomicAdd(&g_S[bh*256 + tid], acc);
}

// ------------------- finalize logits + softmax over d ---------------------
__global__ void k_softmax(const float* __restrict__ temp)
{
    int bh = blockIdx.x; int b = bh >> 2, h = bh & 3;
    int tid = threadIdx.x; int c = tid >> 4, d = tid & 15;
    float nq = fmaxf(sqrtf(g_sqq[b*64 + h*16 + c]), 1e-12f);
    float nk = fmaxf(sqrtf(g_sqk[b*64 + h*16 + d]), 1e-12f);
    float logit = g_S[bh*256 + tid] / (nq*nk) * temp[h];
    float mx = logit;
    #pragma unroll
    for (int off = 8; off; off >>= 1)
        mx = fmaxf(mx, __shfl_xor_sync(0xffffffffu, mx, off, 16));
    float e = expf(logit - mx);
    float s = e;
    #pragma unroll
    for (int off = 8; off; off >>= 1)
        s += __shfl_xor_sync(0xffffffffu, s, off, 16);
    g_attn[bh*256 + tid] = e / s;
}

// ------------------- fused attention-apply + IDCT -------------------------
#define SMP 1028   // padded stride per patch (floats)
__global__ void __launch_bounds__(128) k_applyidct(
    const float* __restrict__ out1, float* __restrict__ out)
{
    __shared__ float sm[8*SMP];
    __shared__ float at[256];
    __shared__ float M[64];
    int bh = blockIdx.y; int b = bh >> 2, h = bh & 3;
    int tid = threadIdx.x;
    if (tid < 64) M[tid] = g_IDCTM[tid];
    at[tid]       = g_attn[bh*256 + tid];
    at[tid + 128] = g_attn[bh*256 + tid + 128];
    int pos0 = blockIdx.x * 8;
    int pp_l = tid >> 4;
    int ab_l = (tid & 15) * 4;
    #pragma unroll 4
    for (int d = 0; d < 16; d++) {
        const float* src = out1 + (((size_t)(b*64 + h*16 + d))*2304 + pos0)*64;
        float4 v = *(const float4*)(src + tid*4);
        *(float4*)(sm + pp_l*SMP + d*64 + ab_l) = v;
    }
    __syncthreads();

    int pp = tid >> 4, cd = tid & 15;
    const float* arow = at + cd*16;
    float X[64];
    #pragma unroll
    for (int i = 0; i < 64; i++) X[i] = 0.f;
    #pragma unroll
    for (int d = 0; d < 16; d++) {
        float av = arow[d];
        const float4* s4 = (const float4*)(sm + pp*SMP + d*64);
        #pragma unroll
        for (int q4 = 0; q4 < 16; q4++) {
            float4 v = s4[q4];
            X[q4*4+0] += av * v.x;
            X[q4*4+1] += av * v.y;
            X[q4*4+2] += av * v.z;
            X[q4*4+3] += av * v.w;
        }
    }
    float tmp[8][8];
    #pragma unroll
    for (int a = 0; a < 8; a++) {
        #pragma unroll
        for (int n = 0; n < 8; n++) {
            float s = 0.f;
            #pragma unroll
            for (int bq = 0; bq < 8; bq++) s += X[a*8+bq] * M[n*8+bq];
            tmp[a][n] = s;
        }
    }
    int pos = pos0 + pp;
    int ph = pos / WW, pw = pos % WW;
    int bc = b*64 + h*16 + cd;
    float* op = out + (size_t)bc*HW + ph*8*Ww + pw*8;
    #pragma unroll
    for (int m = 0; m < 8; m++) {
        float y[8];
        #pragma unroll
        for (int n = 0; n < 8; n++) {
            float s = 0.f;
            #pragma unroll
            for (int a = 0; a < 8; a++) s += M[m*8+a] * tmp[a][n];
            y[n] = s;
        }
        *(float4*)(op + m*Ww)     = make_float4(y[0], y[1], y[2], y[3]);
        *(float4*)(op + m*Ww + 4) = make_float4(y[4], y[5], y[6], y[7]);
    }
}

// ------------------- fully fused pool: both branches, both dw3 stages -----
// out = dw3(prelu(dw3(q*o,w1a),a1),w1b) + dw3(prelu(dw3(v-lam*v*o,w2a),a2),w2b)
// 32x32 output tile per block; t on 36x36, u on 34x34 in smem (halo recompute)
#define TT 36
#define UT 34
__global__ void __launch_bounds__(256) k_poolF(
    const float* __restrict__ q, const float* __restrict__ o,
    const float* __restrict__ kv,
    const float* __restrict__ w1a, const float* __restrict__ w2a,
    const float* __restrict__ a1p, const float* __restrict__ a2p,
    const float* __restrict__ w1b, const float* __restrict__ w2b,
    float* __restrict__ out)
{
    __shared__ float st1[TT*TT], st2[TT*TT];
    __shared__ float su1[UT*UT], su2[UT*UT];
    int tid = threadIdx.x;
    int tx = blockIdx.x % 12, ty = blockIdx.x / 12;
    int x0 = tx*32, y0 = ty*32;
    int bc = blockIdx.y;
    int ch = bc & 63, b = bc >> 6;
    const float* qp = q + (size_t)bc*HW;
    const float* op = o + (size_t)bc*HW;
    const float* vp = kv + ((size_t)b*128 + 64 + ch)*HW;
    float lam = g_lam;

    // phase 1: t1/t2 on 36x36 (zero outside image)
    for (int i = tid; i < TT*TT; i += 256) {
        int ly = i / TT, lx = i - ly*TT;
        int gy = y0 + ly - 2, gx = x0 + lx - 2;
        float t1 = 0.f, t2 = 0.f;
        if ((unsigned)gy < (unsigned)Hh && (unsigned)gx < (unsigned)Ww) {
            int gi = gy*Ww + gx;
            float qv = qp[gi], ov = op[gi], vv = vp[gi];
            t1 = qv * ov;
            t2 = vv - lam * (vv * ov);
        }
        st1[i] = t1; st2[i] = t2;
    }
    float wa1[9], wa2[9];
    #pragma unroll
    for (int i = 0; i < 9; i++) { wa1[i] = __ldg(w1a + ch*9 + i); wa2[i] = __ldg(w2a + ch*9 + i); }
    float a1 = __ldg(a1p), a2 = __ldg(a2p);
    __syncthreads();

    // phase 2: u1/u2 on 34x34 (zero outside image)
    for (int i = tid; i < UT*UT; i += 256) {
        int ly = i / UT, lx = i - ly*UT;
        int gy = y0 + ly - 1, gx = x0 + lx - 1;
        float u1 = 0.f, u2 = 0.f;
        if ((unsigned)gy < (unsigned)Hh && (unsigned)gx < (unsigned)Ww) {
            float s1 = 0.f, s2 = 0.f;
            #pragma unroll
            for (int dy = 0; dy < 3; dy++) {
                const float* r1 = st1 + (ly+dy)*TT + lx;
                const float* r2 = st2 + (ly+dy)*TT + lx;
                #pragma unroll
                for (int dx = 0; dx < 3; dx++) {
                    s1 += wa1[dy*3+dx] * r1[dx];
                    s2 += wa2[dy*3+dx] * r2[dx];
                }
            }
            u1 = (s1 >= 0.f) ? s1 : a1*s1;
            u2 = (s2 >= 0.f) ? s2 : a2*s2;
        }
        su1[i] = u1; su2[i] = u2;
    }
    float wb1[9], wb2[9];
    #pragma unroll
    for (int i = 0; i < 9; i++) { wb1[i] = __ldg(w1b + ch*9 + i); wb2[i] = __ldg(w2b + ch*9 + i); }
    __syncthreads();

    // phase 3: output 32x32
    for (int i = tid; i < 1024; i += 256) {
        int oy = i >> 5, ox = i & 31;
        float s = 0.f;
        #pragma unroll
        for (int dy = 0; dy < 3; dy++) {
            const float* r1 = su1 + (oy+dy)*UT + ox;
            const float* r2 = su2 + (oy+dy)*UT + ox;
            #pragma unroll
            for (int dx = 0; dx < 3; dx++) {
                s += wb1[dy*3+dx] * r1[dx] + wb2[dy*3+dx] * r2[dx];
            }
        }
        out[(size_t)bc*HW + (y0+oy)*Ww + x0 + ox] = s;
    }
}

// ------------------- host launcher ----------------------------------------
extern "C" void kernel_launch(void* const* d_in, const int* in_sizes, int n_in,
                              void* d_out, int out_size)
{
    const float* x            = (const float*)d_in[0];
    const float* nir          = (const float*)d_in[1];
    const float* w_hidden     = (const float*)d_in[2];
    const float* w_hidden_nir = (const float*)d_in[3];
    const float* w_dw         = (const float*)d_in[4];
    const float* w_dw_nir     = (const float*)d_in[5];
    const float* temperature  = (const float*)d_in[6];
    const float* w_proj_mid   = (const float*)d_in[7];
    const float* w_proj_out   = (const float*)d_in[8];
    const float* w_p1a        = (const float*)d_in[9];
    const float* a_p1         = (const float*)d_in[10];
    const float* w_p1b        = (const float*)d_in[11];
    const float* w_p2a        = (const float*)d_in[12];
    const float* a_p2         = (const float*)d_in[13];
    const float* w_p2b        = (const float*)d_in[14];
    const float* lq1          = (const float*)d_in[15];
    const float* lk1          = (const float*)d_in[16];
    const float* lq2          = (const float*)d_in[17];
    const float* lk2          = (const float*)d_in[18];

    float *A, *Bf, *Cf, *D, *E, *F, *G;
    cudaGetSymbolAddress((void**)&A,  g_bA);
    cudaGetSymbolAddress((void**)&Bf, g_bB);
    cudaGetSymbolAddress((void**)&Cf, g_bC);
    cudaGetSymbolAddress((void**)&D,  g_bD);
    cudaGetSymbolAddress((void**)&E,  g_bE);
    cudaGetSymbolAddress((void**)&F,  g_bF);
    cudaGetSymbolAddress((void**)&G,  g_bG);

    const int CONV_SMEM = 98304;   // 32KB weights + 64KB input tile
    cudaFuncSetAttribute(k_conv1x1, cudaFuncAttributeMaxDynamicSharedMemorySize, CONV_SMEM);

    k_init<<<1, 64>>>(lq1, lk1, lq2, lk2);

    // hidden = W_h @ x ; nir_hidden = W_hn @ nir
    k_conv1x1<<<dim3(HW/256, Bb, 1), 256, CONV_SMEM>>>(x,   w_hidden,     A,  64);
    k_conv1x1<<<dim3(HW/256, Bb, 2), 256, CONV_SMEM>>>(nir, w_hidden_nir, Bf, 128);

    // q = dw3(hidden) ; kv = dw3(nir_hidden)
    k_dw3v<<<NTOT/1024,   256>>>(A,  w_dw,     Cf, 63);
    k_dw3v<<<2*NTOT/1024, 256>>>(Bf, w_dw_nir, D,  127);

    // DCTs (fused: qf+sumsq; kf+out1+sumsq)
    k_dctq<<<NPATCH/128, 128>>>(Cf, E);
    k_dctk<<<NPATCH/128, 128>>>(D, E, F, G);

    // attention: Gram -> softmax -> fused apply+IDCT (o_spatial into E)
    k_dot<<<dim3(36, 8), 256>>>(E, F);
    k_softmax<<<8, 256>>>(temperature);
    k_applyidct<<<dim3(HH*WW/8, 8), 128>>>(G, E);

    // out = W_pm @ o
    k_conv1x1<<<dim3(HW/256, Bb, 1), 256, CONV_SMEM>>>(E, w_proj_mid, A, 64);

    // fully fused pools -> G
    k_poolF<<<dim3(144, 128), 256>>>(Cf, A, D, w_p1a, w_p2a, a_p1, a_p2,
                                     w_p1b, w_p2b, G);

    // final projection
    k_conv1x1<<<dim3(HW/256, Bb, 1), 256, CONV_SMEM>>>(G, w_proj_out, (float*)d_out, 64);
}

// round 6
// speedup vs baseline: 1.9306x; 1.0189x over previous
#include <cuda_runtime.h>
#include <math.h>

#define Bb 2
#define Cc 64
#define Hh 384
#define Ww 384
#define HW (Hh*Ww)            // 147456
#define NTOT (Bb*Cc*HW)       // 18874368
#define HH 48
#define WW 48
#define LLEN HW               // 147456
#define NPATCH (Bb*Cc*HH*WW)  // 294912

typedef unsigned long long ull;

// ------------------- scratch (device globals) -----------------------------
__device__ float g_bA[NTOT];      // hidden -> o_spatial
__device__ float g_bB[2*NTOT];    // nir_hidden
__device__ float g_bC[NTOT];      // q
__device__ float g_bD[2*NTOT];    // kv
__device__ float g_bE[NTOT];      // qf -> conv_mid out
__device__ float g_bF[NTOT];      // kf
__device__ float g_bG[NTOT];      // out1 -> pooled output

__device__ float g_DCTM[64];      // [a*8+m]
__device__ float g_IDCTM[64];     // [m*8+a]
__device__ float g_sqq[128];
__device__ float g_sqk[128];
__device__ float g_S[8*256];
__device__ float g_attn[8*256];
__device__ float g_lam;

// ------------------- packed f32x2 helpers (sm_100+) -----------------------
__device__ __forceinline__ ull pk2(float lo, float hi) {
    ull r; asm("mov.b64 %0, {%1,%2};" : "=l"(r) : "f"(lo), "f"(hi)); return r;
}
#define FMA2(d, a, b, c) asm("fma.rn.f32x2 %0, %1, %2, %3;" : "=l"(d) : "l"(a), "l"(b), "l"(c))

// ------------------- init ---------------------------------------------------
__global__ void k_init(const float* __restrict__ lq1, const float* __restrict__ lk1,
                       const float* __restrict__ lq2, const float* __restrict__ lk2)
{
    int t = threadIdx.x;  // 64 threads
    if (t < 64) {
        int a = t >> 3, m = t & 7;
        double cv = 2.0 * cos(3.14159265358979323846 * (double)((2*m+1)*a) / 16.0);
        g_DCTM[a*8+m] = (float)cv;
        g_IDCTM[m*8+a] = (float)(cv / (a == 0 ? 32.0 : 16.0));
    }
    if (t < 32) {
        float s1 = lq1[t]*lk1[t] + lq1[t+32]*lk1[t+32];
        float s2 = lq2[t]*lk2[t] + lq2[t+32]*lk2[t+32];
        #pragma unroll
        for (int off = 16; off; off >>= 1) {
            s1 += __shfl_xor_sync(0xffffffffu, s1, off);
            s2 += __shfl_xor_sync(0xffffffffu, s2, off);
        }
        if (t == 0) {
            float lam_init = 0.8f - 0.6f * (float)exp(-1.8);
            g_lam = expf(s1) - expf(s2) + lam_init;
        }
    }
    for (int i = t; i < 2048; i += 64) g_S[i] = 0.f;
    for (int i = t; i < 128;  i += 64) { g_sqq[i] = 0.f; g_sqk[i] = 0.f; }
}

// ------------------- conv1x1 as smem-tiled GEMM (FFMA2) -------------------
// Block tile: 64 oc x 256 px, k=64. grid=(HW/256, B, nz); oc base = z*64+ocOff
__global__ void __launch_bounds__(256) k_conv1x1(
    const float* __restrict__ in, const float* __restrict__ w,
    float* __restrict__ out, int OCtot, int ocOff)
{
    extern __shared__ char smraw[];
    ull*   ws = (ull*)smraw;                  // [64 oc][64 ic] (w,w)  32KB
    float* xs = (float*)(smraw + 32768);      // [64 ic][256 px]       64KB
    int ocBase = blockIdx.z * 64 + ocOff;
    int b = blockIdx.y;
    int tid = threadIdx.x;

    #pragma unroll
    for (int r = 0; r < 16; r++) {
        int t = r*256 + tid;
        float wv = __ldg(w + ocBase*64 + t);
        ws[t] = pk2(wv, wv);
    }
    const float* inb = in + (size_t)b*64*HW + blockIdx.x*256;
    #pragma unroll
    for (int r = 0; r < 16; r++) {
        int idx = r*256 + tid;        // 0..4095 float4 slots
        int ic  = idx >> 6;
        int c4  = (idx & 63) * 4;
        *(float4*)(xs + ic*256 + c4) = *(const float4*)(inb + (size_t)ic*HW + c4);
    }
    __syncthreads();

    int ocg = tid >> 4;               // 0..15 -> 4 oc
    int pxg = tid & 15;               // 0..15
    int oc0 = ocg * 4;
    int px0 = pxg * 4;                // + 64*t, t=0..3

    ull acc[4][8];
    #pragma unroll
    for (int j = 0; j < 4; j++)
        #pragma unroll
        for (int t = 0; t < 8; t++) acc[j][t] = 0ULL;

    const ull* wbase = ws + oc0*64;
    #pragma unroll 4
    for (int k = 0; k < 64; k++) {
        const float* xr = xs + k*256 + px0;
        ulonglong2 p0 = *(const ulonglong2*)(xr);
        ulonglong2 p1 = *(const ulonglong2*)(xr + 64);
        ulonglong2 p2 = *(const ulonglong2*)(xr + 128);
        ulonglong2 p3 = *(const ulonglong2*)(xr + 192);
        #pragma unroll
        for (int j = 0; j < 4; j++) {
            ull wv = wbase[j*64 + k];
            FMA2(acc[j][0], wv, p0.x, acc[j][0]);
            FMA2(acc[j][1], wv, p0.y, acc[j][1]);
            FMA2(acc[j][2], wv, p1.x, acc[j][2]);
            FMA2(acc[j][3], wv, p1.y, acc[j][3]);
            FMA2(acc[j][4], wv, p2.x, acc[j][4]);
            FMA2(acc[j][5], wv, p2.y, acc[j][5]);
            FMA2(acc[j][6], wv, p3.x, acc[j][6]);
            FMA2(acc[j][7], wv, p3.y, acc[j][7]);
        }
    }

    float* outb = out + ((size_t)b*OCtot + ocBase + oc0)*HW + blockIdx.x*256 + px0;
    #pragma unroll
    for (int j = 0; j < 4; j++) {
        #pragma unroll
        for (int t = 0; t < 4; t++) {
            ulonglong2 v; v.x = acc[j][t*2]; v.y = acc[j][t*2+1];
            *(ulonglong2*)(outb + (size_t)j*HW + t*64) = v;
        }
    }
}

// ------------------- row loader: 6 values around aligned 4-px group -------
__device__ __forceinline__ void load6(const float* __restrict__ row, int x, float v[6])
{
    float4 c = *(const float4*)(row + x);
    v[1] = c.x; v[2] = c.y; v[3] = c.z; v[4] = c.w;
    v[0] = (x > 0)      ? row[x-1] : 0.f;
    v[5] = (x+4 < Ww)   ? row[x+4] : 0.f;
}

// ------------------- depthwise 3x3, 8 px/thread (4 cols x 2 rows) ---------
__global__ void __launch_bounds__(256) k_dw3v2(
    const float* __restrict__ in, const float* __restrict__ w9,
    float* __restrict__ out, int chMask)
{
    int g = blockIdx.x*256 + threadIdx.x;
    int x  = (g % 96) * 4;
    int y  = ((g / 96) % 192) * 2;
    int bc = g / 18432;                 // 96*192
    int ch = bc & chMask;
    const float* ip = in + (size_t)bc*HW;
    float w[9];
    #pragma unroll
    for (int i = 0; i < 9; i++) w[i] = __ldg(w9 + ch*9 + i);

    float vr[4][6];
    #pragma unroll
    for (int r = 0; r < 4; r++) {
        int yy = y - 1 + r;
        if ((unsigned)yy < (unsigned)Hh) load6(ip + yy*Ww, x, vr[r]);
        else { vr[r][0]=0.f; vr[r][1]=0.f; vr[r][2]=0.f; vr[r][3]=0.f; vr[r][4]=0.f; vr[r][5]=0.f; }
    }
    float a0[4] = {0,0,0,0}, a1[4] = {0,0,0,0};
    #pragma unroll
    for (int dy = 0; dy < 3; dy++) {
        const float* wr = w + dy*3;
        #pragma unroll
        for (int j = 0; j < 4; j++) {
            a0[j] += wr[0]*vr[dy][j]   + wr[1]*vr[dy][j+1]   + wr[2]*vr[dy][j+2];
            a1[j] += wr[0]*vr[dy+1][j] + wr[1]*vr[dy+1][j+1] + wr[2]*vr[dy+1][j+2];
        }
    }
    float* op = out + (size_t)bc*HW + y*Ww + x;
    *(float4*)(op)      = make_float4(a0[0], a0[1], a0[2], a0[3]);
    *(float4*)(op + Ww) = make_float4(a1[0], a1[1], a1[2], a1[3]);
}

// ------------------- fused double DCT: qf, kf, out1, both sumsq -----------
// one thread per patch; q-spectrum staged in smem (coef-major, no conflicts)
__global__ void __launch_bounds__(128) k_dct2(
    const float* __restrict__ q, const float* __restrict__ kv,
    float* __restrict__ qf, float* __restrict__ kf, float* __restrict__ out1)
{
    __shared__ float M[64];
    __shared__ float sQ[64*128];      // [coef][tid]  32KB
    __shared__ float redq[4], redk[4];
    int tid = threadIdx.x;
    if (tid < 64) M[tid] = g_DCTM[tid];
    __syncthreads();
    int p = blockIdx.x*128 + tid;
    int pw = p % WW;
    int t2 = p / WW;
    int ph = t2 % HH;
    int bc = t2 / HH;
    int b = bc >> 6, ch = bc & 63;

    // ---- q DCT ----
    const float* ipq = q + (size_t)bc*HW + ph*8*Ww + pw*8;
    float tmp[8][8];
    #pragma unroll
    for (int m = 0; m < 8; m++) {
        float4 v0 = *(const float4*)(ipq + m*Ww);
        float4 v1 = *(const float4*)(ipq + m*Ww + 4);
        float r[8] = {v0.x, v0.y, v0.z, v0.w, v1.x, v1.y, v1.z, v1.w};
        #pragma unroll
        for (int bb = 0; bb < 8; bb++) {
            float s = 0.f;
            #pragma unroll
            for (int n = 0; n < 8; n++) s += r[n] * M[bb*8+n];
            tmp[m][bb] = s;
        }
    }
    float* qp = qf + (size_t)p*64;
    float ssq = 0.f;
    #pragma unroll
    for (int a = 0; a < 8; a++) {
        float y[8];
        #pragma unroll
        for (int bb = 0; bb < 8; bb++) {
            float s = 0.f;
            #pragma unroll
            for (int m = 0; m < 8; m++) s += M[a*8+m] * tmp[m][bb];
            y[bb] = s;
            ssq += s*s;
            sQ[(a*8+bb)*128 + tid] = s;
        }
        *(float4*)(qp + a*8)     = make_float4(y[0], y[1], y[2], y[3]);
        *(float4*)(qp + a*8 + 4) = make_float4(y[4], y[5], y[6], y[7]);
    }

    // ---- k DCT + out1 ----
    const float* ipk = kv + ((size_t)b*128 + ch)*HW + ph*8*Ww + pw*8;
    #pragma unroll
    for (int m = 0; m < 8; m++) {
        float4 v0 = *(const float4*)(ipk + m*Ww);
        float4 v1 = *(const float4*)(ipk + m*Ww + 4);
        float r[8] = {v0.x, v0.y, v0.z, v0.w, v1.x, v1.y, v1.z, v1.w};
        #pragma unroll
        for (int bb = 0; bb < 8; bb++) {
            float s = 0.f;
            #pragma unroll
            for (int n = 0; n < 8; n++) s += r[n] * M[bb*8+n];
            tmp[m][bb] = s;
        }
    }
    float* kp = kf + (size_t)p*64;
    float* o1 = out1 + (size_t)p*64;
    float ssk = 0.f;
    #pragma unroll
    for (int a = 0; a < 8; a++) {
        float y[8], z[8];
        #pragma unroll
        for (int bb = 0; bb < 8; bb++) {
            float s = 0.f;
            #pragma unroll
            for (int m = 0; m < 8; m++) s += M[a*8+m] * tmp[m][bb];
            y[bb] = s;
            ssk += s*s;
            z[bb] = s * sQ[(a*8+bb)*128 + tid];
        }
        *(float4*)(kp + a*8)     = make_float4(y[0], y[1], y[2], y[3]);
        *(float4*)(kp + a*8 + 4) = make_float4(y[4], y[5], y[6], y[7]);
        *(float4*)(o1 + a*8)     = make_float4(z[0], z[1], z[2], z[3]);
        *(float4*)(o1 + a*8 + 4) = make_float4(z[4], z[5], z[6], z[7]);
    }

    #pragma unroll
    for (int off = 16; off; off >>= 1) {
        ssq += __shfl_xor_sync(0xffffffffu, ssq, off);
        ssk += __shfl_xor_sync(0xffffffffu, ssk, off);
    }
    int lane = tid & 31, wd = tid >> 5;
    if (lane == 0) { redq[wd] = ssq; redk[wd] = ssk; }
    __syncthreads();
    if (tid == 0) {
        atomicAdd(&g_sqq[bc], redq[0]+redq[1]+redq[2]+redq[3]);
        atomicAdd(&g_sqk[bc], redk[0]+redk[1]+redk[2]+redk[3]);
    }
}

// ------------------- Gram matrices S[bh][c][d] = <qf_c, kf_d> -------------
__global__ void k_dot(const float* __restrict__ qf, const float* __restrict__ kf)
{
    int bh = blockIdx.y; int b = bh >> 2, h = bh & 3;
    const float* qb = qf + ((size_t)b*64 + h*16)*LLEN;
    const float* kb = kf + ((size_t)b*64 + h*16)*LLEN;
    int tid = threadIdx.x;
    int c = tid >> 4, d = tid & 15;
    __shared__ float qs[16][65], ks[16][65];
    float acc = 0.f;
    int l0 = blockIdx.x * 4096;
    for (int lt = 0; lt < 4096; lt += 64) {
        int base = l0 + lt;
        for (int t = tid; t < 1024; t += 256) {
            int r = t >> 6, i = t & 63;
            qs[r][i] = qb[(size_t)r*LLEN + base + i];
            ks[r][i] = kb[(size_t)r*LLEN + base + i];
        }
        __syncthreads();
        #pragma unroll
        for (int i = 0; i < 64; i++) acc += qs[c][i] * ks[d][i];
        __syncthreads();
    }
    atomicAdd(&g_S[bh*256 + tid], acc);
}

// ------------------- finalize logits + softmax over d ---------------------
__global__ void k_softmax(const float* __restrict__ temp)
{
    int bh = blockIdx.x; int b = bh >> 2, h = bh & 3;
    int tid = threadIdx.x; int c = tid >> 4, d = tid & 15;
    float nq = fmaxf(sqrtf(g_sqq[b*64 + h*16 + c]), 1e-12f);
    float nk = fmaxf(sqrtf(g_sqk[b*64 + h*16 + d]), 1e-12f);
    float logit = g_S[bh*256 + tid] / (nq*nk) * temp[h];
    float mx = logit;
    #pragma unroll
    for (int off = 8; off; off >>= 1)
        mx = fmaxf(mx, __shfl_xor_sync(0xffffffffu, mx, off, 16));
    float e = expf(logit - mx);
    float s = e;
    #pragma unroll
    for (int off = 8; off; off >>= 1)
        s += __shfl_xor_sync(0xffffffffu, s, off, 16);
    g_attn[bh*256 + tid] = e / s;
}

// ------------------- fused attention-apply + IDCT -------------------------
#define SMP 1028   // padded stride per patch (floats)
__global__ void __launch_bounds__(128) k_applyidct(
    const float* __restrict__ out1, float* __restrict__ out)
{
    __shared__ float sm[8*SMP];
    __shared__ float at[256];
    __shared__ float M[64];
    int bh = blockIdx.y; int b = bh >> 2, h = bh & 3;
    int tid = threadIdx.x;
    if (tid < 64) M[tid] = g_IDCTM[tid];
    at[tid]       = g_attn[bh*256 + tid];
    at[tid + 128] = g_attn[bh*256 + tid + 128];
    int pos0 = blockIdx.x * 8;
    int pp_l = tid >> 4;
    int ab_l = (tid & 15) * 4;
    #pragma unroll 4
    for (int d = 0; d < 16; d++) {
        const float* src = out1 + (((size_t)(b*64 + h*16 + d))*2304 + pos0)*64;
        float4 v = *(const float4*)(src + tid*4);
        *(float4*)(sm + pp_l*SMP + d*64 + ab_l) = v;
    }
    __syncthreads();

    int pp = tid >> 4, cd = tid & 15;
    const float* arow = at + cd*16;
    float X[64];
    #pragma unroll
    for (int i = 0; i < 64; i++) X[i] = 0.f;
    #pragma unroll
    for (int d = 0; d < 16; d++) {
        float av = arow[d];
        const float4* s4 = (const float4*)(sm + pp*SMP + d*64);
        #pragma unroll
        for (int q4 = 0; q4 < 16; q4++) {
            float4 v = s4[q4];
            X[q4*4+0] += av * v.x;
            X[q4*4+1] += av * v.y;
            X[q4*4+2] += av * v.z;
            X[q4*4+3] += av * v.w;
        }
    }
    float tmp[8][8];
    #pragma unroll
    for (int a = 0; a < 8; a++) {
        #pragma unroll
        for (int n = 0; n < 8; n++) {
            float s = 0.f;
            #pragma unroll
            for (int bq = 0; bq < 8; bq++) s += X[a*8+bq] * M[n*8+bq];
            tmp[a][n] = s;
        }
    }
    int pos = pos0 + pp;
    int ph = pos / WW, pw = pos % WW;
    int bc = b*64 + h*16 + cd;
    float* op = out + (size_t)bc*HW + ph*8*Ww + pw*8;
    #pragma unroll
    for (int m = 0; m < 8; m++) {
        float y[8];
        #pragma unroll
        for (int n = 0; n < 8; n++) {
            float s = 0.f;
            #pragma unroll
            for (int a = 0; a < 8; a++) s += M[m*8+a] * tmp[a][n];
            y[n] = s;
        }
        *(float4*)(op + m*Ww)     = make_float4(y[0], y[1], y[2], y[3]);
        *(float4*)(op + m*Ww + 4) = make_float4(y[4], y[5], y[6], y[7]);
    }
}

// ------------------- fully fused pool -------------------------------------
#define TT 36
#define UT 34
__global__ void __launch_bounds__(256) k_poolF(
    const float* __restrict__ q, const float* __restrict__ o,
    const float* __restrict__ kv,
    const float* __restrict__ w1a, const float* __restrict__ w2a,
    const float* __restrict__ a1p, const float* __restrict__ a2p,
    const float* __restrict__ w1b, const float* __restrict__ w2b,
    float* __restrict__ out)
{
    __shared__ float st1[TT*TT], st2[TT*TT];
    __shared__ float su1[UT*UT], su2[UT*UT];
    int tid = threadIdx.x;
    int tx = blockIdx.x % 12, ty = blockIdx.x / 12;
    int x0 = tx*32, y0 = ty*32;
    int bc = blockIdx.y;
    int ch = bc & 63, b = bc >> 6;
    const float* qp = q + (size_t)bc*HW;
    const float* op = o + (size_t)bc*HW;
    const float* vp = kv + ((size_t)b*128 + 64 + ch)*HW;
    float lam = g_lam;

    for (int i = tid; i < TT*TT; i += 256) {
        int ly = i / TT, lx = i - ly*TT;
        int gy = y0 + ly - 2, gx = x0 + lx - 2;
        float t1 = 0.f, t2 = 0.f;
        if ((unsigned)gy < (unsigned)Hh && (unsigned)gx < (unsigned)Ww) {
            int gi = gy*Ww + gx;
            float qv = qp[gi], ov = op[gi], vv = vp[gi];
            t1 = qv * ov;
            t2 = vv - lam * (vv * ov);
        }
        st1[i] = t1; st2[i] = t2;
    }
    float wa1[9], wa2[9];
    #pragma unroll
    for (int i = 0; i < 9; i++) { wa1[i] = __ldg(w1a + ch*9 + i); wa2[i] = __ldg(w2a + ch*9 + i); }
    float a1 = __ldg(a1p), a2 = __ldg(a2p);
    __syncthreads();

    for (int i = tid; i < UT*UT; i += 256) {
        int ly = i / UT, lx = i - ly*UT;
        int gy = y0 + ly - 1, gx = x0 + lx - 1;
        float u1 = 0.f, u2 = 0.f;
        if ((unsigned)gy < (unsigned)Hh && (unsigned)gx < (unsigned)Ww) {
            float s1 = 0.f, s2 = 0.f;
            #pragma unroll
            for (int dy = 0; dy < 3; dy++) {
                const float* r1 = st1 + (ly+dy)*TT + lx;
                const float* r2 = st2 + (ly+dy)*TT + lx;
                #pragma unroll
                for (int dx = 0; dx < 3; dx++) {
                    s1 += wa1[dy*3+dx] * r1[dx];
                    s2 += wa2[dy*3+dx] * r2[dx];
                }
            }
            u1 = (s1 >= 0.f) ? s1 : a1*s1;
            u2 = (s2 >= 0.f) ? s2 : a2*s2;
        }
        su1[i] = u1; su2[i] = u2;
    }
    float wb1[9], wb2[9];
    #pragma unroll
    for (int i = 0; i < 9; i++) { wb1[i] = __ldg(w1b + ch*9 + i); wb2[i] = __ldg(w2b + ch*9 + i); }
    __syncthreads();

    for (int i = tid; i < 1024; i += 256) {
        int oy = i >> 5, ox = i & 31;
        float s = 0.f;
        #pragma unroll
        for (int dy = 0; dy < 3; dy++) {
            const float* r1 = su1 + (oy+dy)*UT + ox;
            const float* r2 = su2 + (oy+dy)*UT + ox;
            #pragma unroll
            for (int dx = 0; dx < 3; dx++) {
                s += wb1[dy*3+dx] * r1[dx] + wb2[dy*3+dx] * r2[dx];
            }
        }
        out[(size_t)bc*HW + (y0+oy)*Ww + x0 + ox] = s;
    }
}

// ------------------- host launcher ----------------------------------------
extern "C" void kernel_launch(void* const* d_in, const int* in_sizes, int n_in,
                              void* d_out, int out_size)
{
    const float* x            = (const float*)d_in[0];
    const float* nir          = (const float*)d_in[1];
    const float* w_hidden     = (const float*)d_in[2];
    const float* w_hidden_nir = (const float*)d_in[3];
    const float* w_dw         = (const float*)d_in[4];
    const float* w_dw_nir     = (const float*)d_in[5];
    const float* temperature  = (const float*)d_in[6];
    const float* w_proj_mid   = (const float*)d_in[7];
    const float* w_proj_out   = (const float*)d_in[8];
    const float* w_p1a        = (const float*)d_in[9];
    const float* a_p1         = (const float*)d_in[10];
    const float* w_p1b        = (const float*)d_in[11];
    const float* w_p2a        = (const float*)d_in[12];
    const float* a_p2         = (const float*)d_in[13];
    const float* w_p2b        = (const float*)d_in[14];
    const float* lq1          = (const float*)d_in[15];
    const float* lk1          = (const float*)d_in[16];
    const float* lq2          = (const float*)d_in[17];
    const float* lk2          = (const float*)d_in[18];

    float *A, *Bf, *Cf, *D, *E, *F, *G;
    cudaGetSymbolAddress((void**)&A,  g_bA);
    cudaGetSymbolAddress((void**)&Bf, g_bB);
    cudaGetSymbolAddress((void**)&Cf, g_bC);
    cudaGetSymbolAddress((void**)&D,  g_bD);
    cudaGetSymbolAddress((void**)&E,  g_bE);
    cudaGetSymbolAddress((void**)&F,  g_bF);
    cudaGetSymbolAddress((void**)&G,  g_bG);

    const int CONV_SMEM = 98304;
    cudaFuncSetAttribute(k_conv1x1, cudaFuncAttributeMaxDynamicSharedMemorySize, CONV_SMEM);

    // launch order arranged so the ncu capture (-s 5 -c 1) lands on k_conv1x1
    k_init<<<1, 64>>>(lq1, lk1, lq2, lk2);                                          // 1
    k_conv1x1<<<dim3(HW/256, Bb, 1), 256, CONV_SMEM>>>(x, w_hidden, A, 64, 0);      // 2
    k_dw3v2<<<NTOT/2048, 256>>>(A, w_dw, Cf, 63);                                   // 3
    k_conv1x1<<<dim3(HW/256, Bb, 1), 256, CONV_SMEM>>>(nir, w_hidden_nir, Bf, 128, 0);  // 4
    k_conv1x1<<<dim3(HW/256, Bb, 1), 256, CONV_SMEM>>>(nir, w_hidden_nir, Bf, 128, 64); // 5 <- profiled
    k_dw3v2<<<2*NTOT/2048, 256>>>(Bf, w_dw_nir, D, 127);

    // fused double-DCT: qf(E), kf(F), out1(G), sumsq
    k_dct2<<<NPATCH/128, 128>>>(Cf, D, E, F, G);

    // attention
    k_dot<<<dim3(36, 8), 256>>>(E, F);
    k_softmax<<<8, 256>>>(temperature);
    k_applyidct<<<dim3(HH*WW/8, 8), 128>>>(G, A);   // o_spatial -> A

    // out = W_pm @ o  -> E
    k_conv1x1<<<dim3(HW/256, Bb, 1), 256, CONV_SMEM>>>(A, w_proj_mid, E, 64, 0);

    // fully fused pools -> G
    k_poolF<<<dim3(144, 128), 256>>>(Cf, E, D, w_p1a, w_p2a, a_p1, a_p2,
                                     w_p1b, w_p2b, G);

    // final projection
    k_conv1x1<<<dim3(HW/256, Bb, 1), 256, CONV_SMEM>>>(G, w_proj_out, (float*)d_out, 64, 0);
}

// round 7
// speedup vs baseline: 1.9392x; 1.0044x over previous
#include <cuda_runtime.h>
#include <math.h>

#define Bb 2
#define Cc 64
#define Hh 384
#define Ww 384
#define HW (Hh*Ww)            // 147456
#define NTOT (Bb*Cc*HW)       // 18874368
#define HH 48
#define WW 48
#define LLEN HW               // 147456
#define NPATCH (Bb*Cc*HH*WW)  // 294912

typedef unsigned long long ull;

// ------------------- scratch (device globals) -----------------------------
__device__ float g_bA[NTOT];      // hidden -> o_spatial
__device__ float g_bB[2*NTOT];    // nir_hidden
__device__ float g_bC[NTOT];      // q
__device__ float g_bD[2*NTOT];    // kv
__device__ float g_bE[NTOT];      // qf -> conv_mid out
__device__ float g_bF[NTOT];      // kf
__device__ float g_bG[NTOT];      // out1 -> pooled output

__device__ float g_DCTM[64];      // [a*8+m]
__device__ float g_IDCTM[64];     // [m*8+a]
__device__ float g_sqq[128];
__device__ float g_sqk[128];
__device__ float g_S[8*256];
__device__ float g_attn[8*256];
__device__ float g_lam;

// ------------------- packed f32x2 helpers (sm_100+) -----------------------
__device__ __forceinline__ ull pk2(float lo, float hi) {
    ull r; asm("mov.b64 %0, {%1,%2};" : "=l"(r) : "f"(lo), "f"(hi)); return r;
}
#define FMA2(d, a, b, c) asm("fma.rn.f32x2 %0, %1, %2, %3;" : "=l"(d) : "l"(a), "l"(b), "l"(c))

// ------------------- init ---------------------------------------------------
__global__ void k_init(const float* __restrict__ lq1, const float* __restrict__ lk1,
                       const float* __restrict__ lq2, const float* __restrict__ lk2)
{
    int t = threadIdx.x;  // 64 threads
    if (t < 64) {
        int a = t >> 3, m = t & 7;
        double cv = 2.0 * cos(3.14159265358979323846 * (double)((2*m+1)*a) / 16.0);
        g_DCTM[a*8+m] = (float)cv;
        g_IDCTM[m*8+a] = (float)(cv / (a == 0 ? 32.0 : 16.0));
    }
    if (t < 32) {
        float s1 = lq1[t]*lk1[t] + lq1[t+32]*lk1[t+32];
        float s2 = lq2[t]*lk2[t] + lq2[t+32]*lk2[t+32];
        #pragma unroll
        for (int off = 16; off; off >>= 1) {
            s1 += __shfl_xor_sync(0xffffffffu, s1, off);
            s2 += __shfl_xor_sync(0xffffffffu, s2, off);
        }
        if (t == 0) {
            float lam_init = 0.8f - 0.6f * (float)exp(-1.8);
            g_lam = expf(s1) - expf(s2) + lam_init;
        }
    }
    for (int i = t; i < 2048; i += 64) g_S[i] = 0.f;
    for (int i = t; i < 128;  i += 64) { g_sqq[i] = 0.f; g_sqk[i] = 0.f; }
}

// ------------------- conv1x1 as smem-tiled GEMM (FFMA2) -------------------
// Block tile: 64 oc x 128 px, k=64 (64KB smem -> 3 blocks/SM, 24 warps).
// Thread: 4 oc x 8 px (2 groups of 4 px, stride 64). ~60 regs.
// Per warp-k: 4 bcast LDS.64 + 2 LDS.128 (8 wavefronts) + 16 FFMA2 (32 cyc)
__global__ void __launch_bounds__(256) k_conv1x1(
    const float* __restrict__ in, const float* __restrict__ w,
    float* __restrict__ out, int OCtot, int ocOff)
{
    extern __shared__ char smraw[];
    ull*   ws = (ull*)smraw;                  // [64 oc][64 ic] (w,w)  32KB
    float* xs = (float*)(smraw + 32768);      // [64 ic][128 px]       32KB
    int ocBase = blockIdx.z * 64 + ocOff;
    int b = blockIdx.y;
    int tid = threadIdx.x;

    #pragma unroll
    for (int r = 0; r < 16; r++) {
        int t = r*256 + tid;
        float wv = __ldg(w + ocBase*64 + t);
        ws[t] = pk2(wv, wv);
    }
    const float* inb = in + (size_t)b*64*HW + blockIdx.x*128;
    #pragma unroll
    for (int r = 0; r < 8; r++) {
        int idx = r*256 + tid;        // 0..2047 float4 slots
        int ic  = idx >> 5;
        int c4  = (idx & 31) * 4;
        *(float4*)(xs + ic*128 + c4) = *(const float4*)(inb + (size_t)ic*HW + c4);
    }
    __syncthreads();

    int ocg = tid >> 4;               // 0..15 -> 4 oc
    int pxg = tid & 15;               // 0..15 -> 8 px
    int oc0 = ocg * 4;
    int px0 = pxg * 4;                // + 64*t, t=0..1

    ull acc[4][4];
    #pragma unroll
    for (int j = 0; j < 4; j++)
        #pragma unroll
        for (int t = 0; t < 4; t++) acc[j][t] = 0ULL;

    const ull* wbase = ws + oc0*64;
    #pragma unroll 8
    for (int k = 0; k < 64; k++) {
        const float* xr = xs + k*128 + px0;
        ulonglong2 p0 = *(const ulonglong2*)(xr);
        ulonglong2 p1 = *(const ulonglong2*)(xr + 64);
        #pragma unroll
        for (int j = 0; j < 4; j++) {
            ull wv = wbase[j*64 + k];
            FMA2(acc[j][0], wv, p0.x, acc[j][0]);
            FMA2(acc[j][1], wv, p0.y, acc[j][1]);
            FMA2(acc[j][2], wv, p1.x, acc[j][2]);
            FMA2(acc[j][3], wv, p1.y, acc[j][3]);
        }
    }

    float* outb = out + ((size_t)b*OCtot + ocBase + oc0)*HW + blockIdx.x*128 + px0;
    #pragma unroll
    for (int j = 0; j < 4; j++) {
        ulonglong2 v0; v0.x = acc[j][0]; v0.y = acc[j][1];
        ulonglong2 v1; v1.x = acc[j][2]; v1.y = acc[j][3];
        *(ulonglong2*)(outb + (size_t)j*HW)      = v0;
        *(ulonglong2*)(outb + (size_t)j*HW + 64) = v1;
    }
}

// ------------------- row loader: 6 values around aligned 4-px group -------
__device__ __forceinline__ void load6(const float* __restrict__ row, int x, float v[6])
{
    float4 c = *(const float4*)(row + x);
    v[1] = c.x; v[2] = c.y; v[3] = c.z; v[4] = c.w;
    v[0] = (x > 0)      ? row[x-1] : 0.f;
    v[5] = (x+4 < Ww)   ? row[x+4] : 0.f;
}

// ------------------- depthwise 3x3, 8 px/thread (4 cols x 2 rows) ---------
__global__ void __launch_bounds__(256) k_dw3v2(
    const float* __restrict__ in, const float* __restrict__ w9,
    float* __restrict__ out, int chMask)
{
    int g = blockIdx.x*256 + threadIdx.x;
    int x  = (g % 96) * 4;
    int y  = ((g / 96) % 192) * 2;
    int bc = g / 18432;                 // 96*192
    int ch = bc & chMask;
    const float* ip = in + (size_t)bc*HW;
    float w[9];
    #pragma unroll
    for (int i = 0; i < 9; i++) w[i] = __ldg(w9 + ch*9 + i);

    float vr[4][6];
    #pragma unroll
    for (int r = 0; r < 4; r++) {
        int yy = y - 1 + r;
        if ((unsigned)yy < (unsigned)Hh) load6(ip + yy*Ww, x, vr[r]);
        else { vr[r][0]=0.f; vr[r][1]=0.f; vr[r][2]=0.f; vr[r][3]=0.f; vr[r][4]=0.f; vr[r][5]=0.f; }
    }
    float a0[4] = {0,0,0,0}, a1[4] = {0,0,0,0};
    #pragma unroll
    for (int dy = 0; dy < 3; dy++) {
        const float* wr = w + dy*3;
        #pragma unroll
        for (int j = 0; j < 4; j++) {
            a0[j] += wr[0]*vr[dy][j]   + wr[1]*vr[dy][j+1]   + wr[2]*vr[dy][j+2];
            a1[j] += wr[0]*vr[dy+1][j] + wr[1]*vr[dy+1][j+1] + wr[2]*vr[dy+1][j+2];
        }
    }
    float* op = out + (size_t)bc*HW + y*Ww + x;
    *(float4*)(op)      = make_float4(a0[0], a0[1], a0[2], a0[3]);
    *(float4*)(op + Ww) = make_float4(a1[0], a1[1], a1[2], a1[3]);
}

// ------------------- fused double DCT: qf, kf, out1, both sumsq -----------
__global__ void __launch_bounds__(128) k_dct2(
    const float* __restrict__ q, const float* __restrict__ kv,
    float* __restrict__ qf, float* __restrict__ kf, float* __restrict__ out1)
{
    __shared__ float M[64];
    __shared__ float sQ[64*128];      // [coef][tid]  32KB
    __shared__ float redq[4], redk[4];
    int tid = threadIdx.x;
    if (tid < 64) M[tid] = g_DCTM[tid];
    __syncthreads();
    int p = blockIdx.x*128 + tid;
    int pw = p % WW;
    int t2 = p / WW;
    int ph = t2 % HH;
    int bc = t2 / HH;
    int b = bc >> 6, ch = bc & 63;

    // ---- q DCT ----
    const float* ipq = q + (size_t)bc*HW + ph*8*Ww + pw*8;
    float tmp[8][8];
    #pragma unroll
    for (int m = 0; m < 8; m++) {
        float4 v0 = *(const float4*)(ipq + m*Ww);
        float4 v1 = *(const float4*)(ipq + m*Ww + 4);
        float r[8] = {v0.x, v0.y, v0.z, v0.w, v1.x, v1.y, v1.z, v1.w};
        #pragma unroll
        for (int bb = 0; bb < 8; bb++) {
            float s = 0.f;
            #pragma unroll
            for (int n = 0; n < 8; n++) s += r[n] * M[bb*8+n];
            tmp[m][bb] = s;
        }
    }
    float* qp = qf + (size_t)p*64;
    float ssq = 0.f;
    #pragma unroll
    for (int a = 0; a < 8; a++) {
        float y[8];
        #pragma unroll
        for (int bb = 0; bb < 8; bb++) {
            float s = 0.f;
            #pragma unroll
            for (int m = 0; m < 8; m++) s += M[a*8+m] * tmp[m][bb];
            y[bb] = s;
            ssq += s*s;
            sQ[(a*8+bb)*128 + tid] = s;
        }
        *(float4*)(qp + a*8)     = make_float4(y[0], y[1], y[2], y[3]);
        *(float4*)(qp + a*8 + 4) = make_float4(y[4], y[5], y[6], y[7]);
    }

    // ---- k DCT + out1 ----
    const float* ipk = kv + ((size_t)b*128 + ch)*HW + ph*8*Ww + pw*8;
    #pragma unroll
    for (int m = 0; m < 8; m++) {
        float4 v0 = *(const float4*)(ipk + m*Ww);
        float4 v1 = *(const float4*)(ipk + m*Ww + 4);
        float r[8] = {v0.x, v0.y, v0.z, v0.w, v1.x, v1.y, v1.z, v1.w};
        #pragma unroll
        for (int bb = 0; bb < 8; bb++) {
            float s = 0.f;
            #pragma unroll
            for (int n = 0; n < 8; n++) s += r[n] * M[bb*8+n];
            tmp[m][bb] = s;
        }
    }
    float* kp = kf + (size_t)p*64;
    float* o1 = out1 + (size_t)p*64;
    float ssk = 0.f;
    #pragma unroll
    for (int a = 0; a < 8; a++) {
        float y[8], z[8];
        #pragma unroll
        for (int bb = 0; bb < 8; bb++) {
            float s = 0.f;
            #pragma unroll
            for (int m = 0; m < 8; m++) s += M[a*8+m] * tmp[m][bb];
            y[bb] = s;
            ssk += s*s;
            z[bb] = s * sQ[(a*8+bb)*128 + tid];
        }
        *(float4*)(kp + a*8)     = make_float4(y[0], y[1], y[2], y[3]);
        *(float4*)(kp + a*8 + 4) = make_float4(y[4], y[5], y[6], y[7]);
        *(float4*)(o1 + a*8)     = make_float4(z[0], z[1], z[2], z[3]);
        *(float4*)(o1 + a*8 + 4) = make_float4(z[4], z[5], z[6], z[7]);
    }

    #pragma unroll
    for (int off = 16; off; off >>= 1) {
        ssq += __shfl_xor_sync(0xffffffffu, ssq, off);
        ssk += __shfl_xor_sync(0xffffffffu, ssk, off);
    }
    int lane = tid & 31, wd = tid >> 5;
    if (lane == 0) { redq[wd] = ssq; redk[wd] = ssk; }
    __syncthreads();
    if (tid == 0) {
        atomicAdd(&g_sqq[bc], redq[0]+redq[1]+redq[2]+redq[3]);
        atomicAdd(&g_sqk[bc], redk[0]+redk[1]+redk[2]+redk[3]);
    }
}

// ------------------- Gram matrices S[bh][c][d] = <qf_c, kf_d> -------------
__global__ void k_dot(const float* __restrict__ qf, const float* __restrict__ kf)
{
    int bh = blockIdx.y; int b = bh >> 2, h = bh & 3;
    const float* qb = qf + ((size_t)b*64 + h*16)*LLEN;
    const float* kb = kf + ((size_t)b*64 + h*16)*LLEN;
    int tid = threadIdx.x;
    int c = tid >> 4, d = tid & 15;
    __shared__ float qs[16][65], ks[16][65];
    float acc = 0.f;
    int l0 = blockIdx.x * 4096;
    for (int lt = 0; lt < 4096; lt += 64) {
        int base = l0 + lt;
        for (int t = tid; t < 1024; t += 256) {
            int r = t >> 6, i = t & 63;
            qs[r][i] = qb[(size_t)r*LLEN + base + i];
            ks[r][i] = kb[(size_t)r*LLEN + base + i];
        }
        __syncthreads();
        #pragma unroll
        for (int i = 0; i < 64; i++) acc += qs[c][i] * ks[d][i];
        __syncthreads();
    }
    atomicAdd(&g_S[bh*256 + tid], acc);
}

// ------------------- finalize logits + softmax over d ---------------------
__global__ void k_softmax(const float* __restrict__ temp)
{
    int bh = blockIdx.x; int b = bh >> 2, h = bh & 3;
    int tid = threadIdx.x; int c = tid >> 4, d = tid & 15;
    float nq = fmaxf(sqrtf(g_sqq[b*64 + h*16 + c]), 1e-12f);
    float nk = fmaxf(sqrtf(g_sqk[b*64 + h*16 + d]), 1e-12f);
    float logit = g_S[bh*256 + tid] / (nq*nk) * temp[h];
    float mx = logit;
    #pragma unroll
    for (int off = 8; off; off >>= 1)
        mx = fmaxf(mx, __shfl_xor_sync(0xffffffffu, mx, off, 16));
    float e = expf(logit - mx);
    float s = e;
    #pragma unroll
    for (int off = 8; off; off >>= 1)
        s += __shfl_xor_sync(0xffffffffu, s, off, 16);
    g_attn[bh*256 + tid] = e / s;
}

// ------------------- fused attention-apply + IDCT -------------------------
#define SMP 1028   // padded stride per patch (floats)
__global__ void __launch_bounds__(128) k_applyidct(
    const float* __restrict__ out1, float* __restrict__ out)
{
    __shared__ float sm[8*SMP];
    __shared__ float at[256];
    __shared__ float M[64];
    int bh = blockIdx.y; int b = bh >> 2, h = bh & 3;
    int tid = threadIdx.x;
    if (tid < 64) M[tid] = g_IDCTM[tid];
    at[tid]       = g_attn[bh*256 + tid];
    at[tid + 128] = g_attn[bh*256 + tid + 128];
    int pos0 = blockIdx.x * 8;
    int pp_l = tid >> 4;
    int ab_l = (tid & 15) * 4;
    #pragma unroll 4
    for (int d = 0; d < 16; d++) {
        const float* src = out1 + (((size_t)(b*64 + h*16 + d))*2304 + pos0)*64;
        float4 v = *(const float4*)(src + tid*4);
        *(float4*)(sm + pp_l*SMP + d*64 + ab_l) = v;
    }
    __syncthreads();

    int pp = tid >> 4, cd = tid & 15;
    const float* arow = at + cd*16;
    float X[64];
    #pragma unroll
    for (int i = 0; i < 64; i++) X[i] = 0.f;
    #pragma unroll
    for (int d = 0; d < 16; d++) {
        float av = arow[d];
        const float4* s4 = (const float4*)(sm + pp*SMP + d*64);
        #pragma unroll
        for (int q4 = 0; q4 < 16; q4++) {
            float4 v = s4[q4];
            X[q4*4+0] += av * v.x;
            X[q4*4+1] += av * v.y;
            X[q4*4+2] += av * v.z;
            X[q4*4+3] += av * v.w;
        }
    }
    float tmp[8][8];
    #pragma unroll
    for (int a = 0; a < 8; a++) {
        #pragma unroll
        for (int n = 0; n < 8; n++) {
            float s = 0.f;
            #pragma unroll
            for (int bq = 0; bq < 8; bq++) s += X[a*8+bq] * M[n*8+bq];
            tmp[a][n] = s;
        }
    }
    int pos = pos0 + pp;
    int ph = pos / WW, pw = pos % WW;
    int bc = b*64 + h*16 + cd;
    float* op = out + (size_t)bc*HW + ph*8*Ww + pw*8;
    #pragma unroll
    for (int m = 0; m < 8; m++) {
        float y[8];
        #pragma unroll
        for (int n = 0; n < 8; n++) {
            float s = 0.f;
            #pragma unroll
            for (int a = 0; a < 8; a++) s += M[m*8+a] * tmp[a][n];
            y[n] = s;
        }
        *(float4*)(op + m*Ww)     = make_float4(y[0], y[1], y[2], y[3]);
        *(float4*)(op + m*Ww + 4) = make_float4(y[4], y[5], y[6], y[7]);
    }
}

// ------------------- fully fused pool -------------------------------------
#define TT 36
#define UT 34
__global__ void __launch_bounds__(256) k_poolF(
    const float* __restrict__ q, const float* __restrict__ o,
    const float* __restrict__ kv,
    const float* __restrict__ w1a, const float* __restrict__ w2a,
    const float* __restrict__ a1p, const float* __restrict__ a2p,
    const float* __restrict__ w1b, const float* __restrict__ w2b,
    float* __restrict__ out)
{
    __shared__ float st1[TT*TT], st2[TT*TT];
    __shared__ float su1[UT*UT], su2[UT*UT];
    int tid = threadIdx.x;
    int tx = blockIdx.x % 12, ty = blockIdx.x / 12;
    int x0 = tx*32, y0 = ty*32;
    int bc = blockIdx.y;
    int ch = bc & 63, b = bc >> 6;
    const float* qp = q + (size_t)bc*HW;
    const float* op = o + (size_t)bc*HW;
    const float* vp = kv + ((size_t)b*128 + 64 + ch)*HW;
    float lam = g_lam;

    for (int i = tid; i < TT*TT; i += 256) {
        int ly = i / TT, lx = i - ly*TT;
        int gy = y0 + ly - 2, gx = x0 + lx - 2;
        float t1 = 0.f, t2 = 0.f;
        if ((unsigned)gy < (unsigned)Hh && (unsigned)gx < (unsigned)Ww) {
            int gi = gy*Ww + gx;
            float qv = qp[gi], ov = op[gi], vv = vp[gi];
            t1 = qv * ov;
            t2 = vv - lam * (vv * ov);
        }
        st1[i] = t1; st2[i] = t2;
    }
    float wa1[9], wa2[9];
    #pragma unroll
    for (int i = 0; i < 9; i++) { wa1[i] = __ldg(w1a + ch*9 + i); wa2[i] = __ldg(w2a + ch*9 + i); }
    float a1 = __ldg(a1p), a2 = __ldg(a2p);
    __syncthreads();

    for (int i = tid; i < UT*UT; i += 256) {
        int ly = i / UT, lx = i - ly*UT;
        int gy = y0 + ly - 1, gx = x0 + lx - 1;
        float u1 = 0.f, u2 = 0.f;
        if ((unsigned)gy < (unsigned)Hh && (unsigned)gx < (unsigned)Ww) {
            float s1 = 0.f, s2 = 0.f;
            #pragma unroll
            for (int dy = 0; dy < 3; dy++) {
                const float* r1 = st1 + (ly+dy)*TT + lx;
                const float* r2 = st2 + (ly+dy)*TT + lx;
                #pragma unroll
                for (int dx = 0; dx < 3; dx++) {
                    s1 += wa1[dy*3+dx] * r1[dx];
                    s2 += wa2[dy*3+dx] * r2[dx];
                }
            }
            u1 = (s1 >= 0.f) ? s1 : a1*s1;
            u2 = (s2 >= 0.f) ? s2 : a2*s2;
        }
        su1[i] = u1; su2[i] = u2;
    }
    float wb1[9], wb2[9];
    #pragma unroll
    for (int i = 0; i < 9; i++) { wb1[i] = __ldg(w1b + ch*9 + i); wb2[i] = __ldg(w2b + ch*9 + i); }
    __syncthreads();

    for (int i = tid; i < 1024; i += 256) {
        int oy = i >> 5, ox = i & 31;
        float s = 0.f;
        #pragma unroll
        for (int dy = 0; dy < 3; dy++) {
            const float* r1 = su1 + (oy+dy)*UT + ox;
            const float* r2 = su2 + (oy+dy)*UT + ox;
            #pragma unroll
            for (int dx = 0; dx < 3; dx++) {
                s += wb1[dy*3+dx] * r1[dx] + wb2[dy*3+dx] * r2[dx];
            }
        }
        out[(size_t)bc*HW + (y0+oy)*Ww + x0 + ox] = s;
    }
}

// ------------------- host launcher ----------------------------------------
extern "C" void kernel_launch(void* const* d_in, const int* in_sizes, int n_in,
                              void* d_out, int out_size)
{
    const float* x            = (const float*)d_in[0];
    const float* nir          = (const float*)d_in[1];
    const float* w_hidden     = (const float*)d_in[2];
    const float* w_hidden_nir = (const float*)d_in[3];
    const float* w_dw         = (const float*)d_in[4];
    const float* w_dw_nir     = (const float*)d_in[5];
    const float* temperature  = (const float*)d_in[6];
    const float* w_proj_mid   = (const float*)d_in[7];
    const float* w_proj_out   = (const float*)d_in[8];
    const float* w_p1a        = (const float*)d_in[9];
    const float* a_p1         = (const float*)d_in[10];
    const float* w_p1b        = (const float*)d_in[11];
    const float* w_p2a        = (const float*)d_in[12];
    const float* a_p2         = (const float*)d_in[13];
    const float* w_p2b        = (const float*)d_in[14];
    const float* lq1          = (const float*)d_in[15];
    const float* lk1          = (const float*)d_in[16];
    const float* lq2          = (const float*)d_in[17];
    const float* lk2          = (const float*)d_in[18];

    float *A, *Bf, *Cf, *D, *E, *F, *G;
    cudaGetSymbolAddress((void**)&A,  g_bA);
    cudaGetSymbolAddress((void**)&Bf, g_bB);
    cudaGetSymbolAddress((void**)&Cf, g_bC);
    cudaGetSymbolAddress((void**)&D,  g_bD);
    cudaGetSymbolAddress((void**)&E,  g_bE);
    cudaGetSymbolAddress((void**)&F,  g_bF);
    cudaGetSymbolAddress((void**)&G,  g_bG);

    const int CONV_SMEM = 65536;   // 32KB weights + 32KB input tile
    cudaFuncSetAttribute(k_conv1x1, cudaFuncAttributeMaxDynamicSharedMemorySize, CONV_SMEM);

    // launch order arranged so the ncu capture (-s 5 -c 1) lands on k_conv1x1
    k_init<<<1, 64>>>(lq1, lk1, lq2, lk2);                                          // 1
    k_conv1x1<<<dim3(HW/128, Bb, 1), 256, CONV_SMEM>>>(x, w_hidden, A, 64, 0);      // 2
    k_dw3v2<<<NTOT/2048, 256>>>(A, w_dw, Cf, 63);                                   // 3
    k_conv1x1<<<dim3(HW/128, Bb, 1), 256, CONV_SMEM>>>(nir, w_hidden_nir, Bf, 128, 0);  // 4
    k_conv1x1<<<dim3(HW/128, Bb, 1), 256, CONV_SMEM>>>(nir, w_hidden_nir, Bf, 128, 64); // 5 <- profiled
    k_dw3v2<<<2*NTOT/2048, 256>>>(Bf, w_dw_nir, D, 127);

    // fused double-DCT: qf(E), kf(F), out1(G), sumsq
    k_dct2<<<NPATCH/128, 128>>>(Cf, D, E, F, G);

    // attention
    k_dot<<<dim3(36, 8), 256>>>(E, F);
    k_softmax<<<8, 256>>>(temperature);
    k_applyidct<<<dim3(HH*WW/8, 8), 128>>>(G, A);   // o_spatial -> A

    // out = W_pm @ o  -> E
    k_conv1x1<<<dim3(HW/128, Bb, 1), 256, CONV_SMEM>>>(A, w_proj_mid, E, 64, 0);

    // fully fused pools -> G
    k_poolF<<<dim3(144, 128), 256>>>(Cf, E, D, w_p1a, w_p2a, a_p1, a_p2,
                                     w_p1b, w_p2b, G);

    // final projection
    k_conv1x1<<<dim3(HW/128, Bb, 1), 256, CONV_SMEM>>>(G, w_proj_out, (float*)d_out, 64, 0);
}